// round 14
// baseline (speedup 1.0000x reference)
#include <cuda_runtime.h>
#include <cuda_bf16.h>
#include <cstdint>
#include <math.h>

// Problem constants
#define B_    4
#define SQ_   1024
#define SKV_  4096
#define DQ_   1024
#define DKV_  768
#define H_    16
#define DH_   64
#define DOUT_ 256

#define SWZ(o) ((o) ^ (((o) >> 3) & 0x70))

// ---------------------------------------------------------------------------
// Scratch
// ---------------------------------------------------------------------------
#define AL16 __align__(16)
__device__ AL16 __nv_bfloat16 g_sqh[(size_t)B_ * SQ_  * DQ_ ], g_sql[(size_t)B_ * SQ_  * DQ_ ];
__device__ AL16 __nv_bfloat16 g_skh[(size_t)B_ * SKV_ * DKV_], g_skl[(size_t)B_ * SKV_ * DKV_];
__device__ AL16 __nv_bfloat16 g_svh[(size_t)B_ * SKV_ * DKV_], g_svl[(size_t)B_ * SKV_ * DKV_];
__device__ AL16 __nv_bfloat16 g_wqh[DQ_ * DQ_ ],  g_wql[DQ_ * DQ_ ];
__device__ AL16 __nv_bfloat16 g_wkh[DQ_ * DKV_],  g_wkl[DQ_ * DKV_];
__device__ AL16 __nv_bfloat16 g_wvh[DQ_ * DKV_],  g_wvl[DQ_ * DKV_];
__device__ AL16 __nv_bfloat16 g_woh[DOUT_ * DQ_], g_wol[DOUT_ * DQ_];
__device__ AL16 __nv_bfloat16 g_qh [(size_t)B_ * SQ_  * DQ_], g_ql [(size_t)B_ * SQ_  * DQ_];
__device__ AL16 __nv_bfloat16 g_kh [(size_t)B_ * SKV_ * DQ_], g_kl [(size_t)B_ * SKV_ * DQ_];
__device__ AL16 __nv_bfloat16 g_vth[(size_t)B_ * DQ_ * SKV_], g_vtl[(size_t)B_ * DQ_ * SKV_];
__device__ AL16 __nv_bfloat16 g_ath[(size_t)B_ * SQ_ * DQ_], g_atl[(size_t)B_ * SQ_ * DQ_];
__device__ AL16 unsigned char g_maskT[(size_t)B_ * SQ_ * SKV_];
#define NROWS_ (B_ * H_ * SQ_)
#define NTILES_ (SKV_ / 64)
__device__ AL16 float g_gmax[(size_t)NROWS_ * NTILES_];
__device__ AL16 float g_gsum[(size_t)NROWS_ * NTILES_];
__device__ AL16 float g_rowM[NROWS_];
__device__ AL16 float g_rowI[NROWS_];
__device__ int g_mask_flag;

// ---------------------------------------------------------------------------
// Mask dtype probe
// ---------------------------------------------------------------------------
__global__ void probe_mask_kernel(const unsigned int* __restrict__ m)
{
    if (blockIdx.x != 0 || threadIdx.x != 0) return;
    int is_i32 = 1, is_f32 = 1;
    for (int i = 0; i < 4096; i++) {
        unsigned v = m[i];
        if (v > 1u) is_i32 = 0;
        if (v != 0u && v != 0x3F800000u) is_f32 = 0;
    }
    g_mask_flag = is_i32 ? 1 : (is_f32 ? 2 : 0);
}

__device__ __forceinline__ bool read_mask(const void* m, long i, int flag)
{
    if (flag == 1) return ((const int*)m)[i] != 0;
    if (flag == 2) return ((const float*)m)[i] != 0.0f;
    return ((const unsigned char*)m)[i] != 0;
}

// ---------------------------------------------------------------------------
// Mask transpose: mask[b][kv][q] -> u8 maskT[b][q][kv]
// ---------------------------------------------------------------------------
__global__ __launch_bounds__(256)
void transpose_mask_kernel(const void* __restrict__ mask,
                           unsigned char* __restrict__ maskT)
{
    __shared__ unsigned char t[32][33];
    const int b   = blockIdx.z;
    const int kv0 = blockIdx.x * 32, q0 = blockIdx.y * 32;
    const int x = threadIdx.x, y = threadIdx.y;
    const int flag = g_mask_flag;
#pragma unroll
    for (int i = y; i < 32; i += 8)
        t[i][x] = read_mask(mask, ((long)b * SKV_ + kv0 + i) * SQ_ + q0 + x, flag) ? 1 : 0;
    __syncthreads();
#pragma unroll
    for (int i = y; i < 32; i += 8)
        maskT[((long)b * SQ_ + q0 + i) * SKV_ + kv0 + x] = t[x][i];
}

// ---------------------------------------------------------------------------
// Primitives
// ---------------------------------------------------------------------------
__device__ __forceinline__ uint32_t smem_to_u32(const void* p) {
    uint32_t a;
    asm("{ .reg .u64 t; cvta.to.shared.u64 t, %1; cvt.u32.u64 %0, t; }"
        : "=r"(a) : "l"(p));
    return a;
}

__device__ __forceinline__ void ldm_x4(uint32_t addr, uint32_t* r) {
    asm volatile("ldmatrix.sync.aligned.m8n8.x4.shared.b16 {%0,%1,%2,%3}, [%4];"
                 : "=r"(r[0]), "=r"(r[1]), "=r"(r[2]), "=r"(r[3]) : "r"(addr));
}

__device__ __forceinline__ void mma_bf16(float* d, const uint32_t* a,
                                         uint32_t b0, uint32_t b1) {
    asm volatile(
        "mma.sync.aligned.m16n8k16.row.col.f32.bf16.bf16.f32 "
        "{%0,%1,%2,%3}, {%4,%5,%6,%7}, {%8,%9}, {%0,%1,%2,%3};"
        : "+f"(d[0]), "+f"(d[1]), "+f"(d[2]), "+f"(d[3])
        : "r"(a[0]), "r"(a[1]), "r"(a[2]), "r"(a[3]), "r"(b0), "r"(b1));
}

__device__ __forceinline__ uint32_t pk2(__nv_bfloat16 a, __nv_bfloat16 b)
{
    return (uint32_t)__bfloat16_as_ushort(a) | ((uint32_t)__bfloat16_as_ushort(b) << 16);
}

__device__ __forceinline__ void cvt1(float4 v, char* hb, char* lb, int r, int cg)
{
    __nv_bfloat16 h0 = __float2bfloat16(v.x);
    __nv_bfloat16 h1 = __float2bfloat16(v.y);
    __nv_bfloat16 h2 = __float2bfloat16(v.z);
    __nv_bfloat16 h3 = __float2bfloat16(v.w);
    __nv_bfloat16 l0 = __float2bfloat16(v.x - __bfloat162float(h0));
    __nv_bfloat16 l1 = __float2bfloat16(v.y - __bfloat162float(h1));
    __nv_bfloat16 l2 = __float2bfloat16(v.z - __bfloat162float(h2));
    __nv_bfloat16 l3 = __float2bfloat16(v.w - __bfloat162float(h3));
    unsigned off = SWZ((unsigned)(r * 128 + (cg << 1)));
    *(uint2*)(hb + off) = make_uint2(pk2(h0, h1), pk2(h2, h3));
    *(uint2*)(lb + off) = make_uint2(pk2(l0, l1), pk2(l2, l3));
}

template<int ROWS>
__device__ __forceinline__ void cpa_tile(uint32_t dst, const __nv_bfloat16* src,
                                         int ld, int tid)
{
#pragma unroll
    for (int i = 0; i < ROWS / 32; i++) {
        int f = tid + i * 256;
        int r = f >> 3, c = f & 7;
        uint32_t d = dst + SWZ((unsigned)(r * 128 + c * 16));
        const void* s = src + (long)r * ld + c * 8;
        asm volatile("cp.async.cg.shared.global [%0], [%1], 16;" :: "r"(d), "l"(s));
    }
}

template<int ROWS>
__device__ __forceinline__ void cpa_tile512(uint32_t dst, const __nv_bfloat16* src,
                                            int ld, int tid)
{
#pragma unroll
    for (int i = 0; i < ROWS / 64; i++) {
        int f = tid + i * 512;
        int r = f >> 3, c = f & 7;
        uint32_t d = dst + SWZ((unsigned)(r * 128 + c * 16));
        const void* s = src + (long)r * ld + c * 8;
        asm volatile("cp.async.cg.shared.global [%0], [%1], 16;" :: "r"(d), "l"(s));
    }
}

// ---------------------------------------------------------------------------
// Merged fp32 -> bf16 hi/lo split for all 7 operands
// ---------------------------------------------------------------------------
__device__ __forceinline__ void split_body(const float* src,
                                           __nv_bfloat16* h, __nv_bfloat16* l,
                                           long blk, int tid)
{
    long i = (blk * 256 + tid) * 4;
    float4 v = *(const float4*)(src + i);
    __nv_bfloat16 h0 = __float2bfloat16(v.x), h1 = __float2bfloat16(v.y);
    __nv_bfloat16 h2 = __float2bfloat16(v.z), h3 = __float2bfloat16(v.w);
    *(uint2*)(h + i) = make_uint2(pk2(h0, h1), pk2(h2, h3));
    *(uint2*)(l + i) = make_uint2(
        pk2(__float2bfloat16(v.x - __bfloat162float(h0)),
            __float2bfloat16(v.y - __bfloat162float(h1))),
        pk2(__float2bfloat16(v.z - __bfloat162float(h2)),
            __float2bfloat16(v.w - __bfloat162float(h3))));
}

__global__ __launch_bounds__(256)
void split_all_kernel(const float* __restrict__ Q, const float* __restrict__ K,
                      const float* __restrict__ V, const float* __restrict__ Wq,
                      const float* __restrict__ Wk, const float* __restrict__ Wv,
                      const float* __restrict__ Wo,
                      __nv_bfloat16* sqh, __nv_bfloat16* sql,
                      __nv_bfloat16* skh, __nv_bfloat16* skl,
                      __nv_bfloat16* svh, __nv_bfloat16* svl,
                      __nv_bfloat16* wqh, __nv_bfloat16* wql,
                      __nv_bfloat16* wkh, __nv_bfloat16* wkl,
                      __nv_bfloat16* wvh, __nv_bfloat16* wvl,
                      __nv_bfloat16* woh, __nv_bfloat16* wol)
{
    const int bx = blockIdx.x, tid = threadIdx.x;
    if      (bx < 4096)  split_body(Q,  sqh, sql, bx,          tid);
    else if (bx < 16384) split_body(K,  skh, skl, bx - 4096,   tid);
    else if (bx < 28672) split_body(V,  svh, svl, bx - 16384,  tid);
    else if (bx < 29696) split_body(Wq, wqh, wql, bx - 28672,  tid);
    else if (bx < 30464) split_body(Wk, wkh, wkl, bx - 29696,  tid);
    else if (bx < 31232) split_body(Wv, wvh, wvl, bx - 30464,  tid);
    else                 split_body(Wo, woh, wol, bx - 31232,  tid);
}

// ---------------------------------------------------------------------------
// Stats combine
// ---------------------------------------------------------------------------
__global__ __launch_bounds__(256)
void stats_combine_kernel(const float* __restrict__ gmax,
                          const float* __restrict__ gsum,
                          float* __restrict__ rowM, float* __restrict__ rowI)
{
    const int row  = blockIdx.x * 8 + (threadIdx.x >> 5);
    const int lane = threadIdx.x & 31;
    float m0 = gmax[(long)row * NTILES_ + lane];
    float m1 = gmax[(long)row * NTILES_ + lane + 32];
    float s0 = gsum[(long)row * NTILES_ + lane];
    float s1 = gsum[(long)row * NTILES_ + lane + 32];
    float M = fmaxf(m0, m1);
#pragma unroll
    for (int o = 16; o; o >>= 1) M = fmaxf(M, __shfl_xor_sync(0xFFFFFFFFu, M, o));
    float sc = s0 * __expf(m0 - M) + s1 * __expf(m1 - M);
#pragma unroll
    for (int o = 16; o; o >>= 1) sc += __shfl_xor_sync(0xFFFFFFFFu, sc, o);
    if (lane == 0) { rowM[row] = M; rowI[row] = 1.0f / sc; }
}

// ---------------------------------------------------------------------------
// 512-thread 3-stage GEMM, 128x128 tile, single barrier per K-slab.
// MODE 0: +bias, write bf16 h/l    (Q/K projections)
// MODE 3: +bias, write fp32        (Wo)
// MODE 4: +bias, write bf16 h/l TRANSPOSED to vt[b][ch][kv] (V projection)
// ---------------------------------------------------------------------------
template<int MODE>
__global__ void __launch_bounds__(512, 1)
hgemm512_kernel(const __nv_bfloat16* __restrict__ Ah, const __nv_bfloat16* __restrict__ Al, int lda,
                const __nv_bfloat16* __restrict__ Bh, const __nv_bfloat16* __restrict__ Bl, int ldb,
                const float* __restrict__ bias,
                void* __restrict__ C0, void* __restrict__ C1, int ldc, int Kdim)
{
    extern __shared__ char smem[];
    constexpr unsigned PBY = 16384u;            // bytes per 128x64 bf16 part
    constexpr unsigned STG = 4 * PBY;           // 64KB per stage

    const uint32_t sbase = smem_to_u32(smem);
    const int tid = threadIdx.x;
    const int wid = tid >> 5, lid = tid & 31;
    const int wm = wid & 3, wn = wid >> 2;      // 4(m) x 4(n)
    const int m0 = blockIdx.y * 128, n0 = blockIdx.x * 128;

    const __nv_bfloat16* Aph = Ah + (long)m0 * lda;
    const __nv_bfloat16* Apl = Al + (long)m0 * lda;
    const __nv_bfloat16* Bph = Bh + (long)n0 * ldb;
    const __nv_bfloat16* Bpl = Bl + (long)n0 * ldb;
    const int LDA = lda, LDB = ldb, LDC = ldc;

    float dc[8][4];
#pragma unroll
    for (int i = 0; i < 8; i++)
#pragma unroll
        for (int j = 0; j < 4; j++) dc[i][j] = 0.0f;

    const int ns = Kdim >> 6;

    auto issue = [&](int s) {
        uint32_t base = sbase + (unsigned)(s % 3) * STG;
        cpa_tile512<128>(base,           Aph + (long)s * 64, LDA, tid);
        cpa_tile512<128>(base + PBY,     Apl + (long)s * 64, LDA, tid);
        cpa_tile512<128>(base + 2 * PBY, Bph + (long)s * 64, LDB, tid);
        cpa_tile512<128>(base + 3 * PBY, Bpl + (long)s * 64, LDB, tid);
        asm volatile("cp.async.commit_group;" ::: "memory");
    };

    auto compute = [&](int buf) {
        const uint32_t sA  = sbase + (unsigned)buf * STG;
        const uint32_t sAl = sA + PBY;
        const uint32_t sB  = sA + 2 * PBY;
        const uint32_t sBl = sA + 3 * PBY;
        const int lr = lid & 15, hsel = (lid >> 4) << 4;
#pragma unroll
        for (int ks = 0; ks < 4; ks++) {
            const int kb = ks * 32 + hsel;
            uint32_t aH[2][4], aL[2][4];
#pragma unroll
            for (int i = 0; i < 2; i++) {
                unsigned off = SWZ((unsigned)((wm * 32 + i * 16 + lr) * 128 + kb));
                ldm_x4(sA + off, aH[i]);
                ldm_x4(sAl + off, aL[i]);
            }
#pragma unroll
            for (int jj = 0; jj < 2; jj++) {
                unsigned off = SWZ((unsigned)((wn * 32 + jj * 16 + lr) * 128 + kb));
                uint32_t bH[4], bL[4];
                ldm_x4(sB + off, bH);
                ldm_x4(sBl + off, bL);
#pragma unroll
                for (int i = 0; i < 2; i++) {
#pragma unroll
                    for (int t = 0; t < 2; t++) {
                        float* d = dc[i * 4 + jj * 2 + t];
                        mma_bf16(d, aH[i], bH[t], bH[t + 2]);
                        mma_bf16(d, aH[i], bL[t], bL[t + 2]);
                        mma_bf16(d, aL[i], bH[t], bH[t + 2]);
                    }
                }
            }
        }
    };

    issue(0); issue(1);
    for (int s = 0; s < ns; s++) {
        if (s + 1 < ns) asm volatile("cp.async.wait_group 1;" ::: "memory");
        else            asm volatile("cp.async.wait_group 0;" ::: "memory");
        __syncthreads();
        compute(s % 3);
        if (s + 2 < ns) issue(s + 2);
    }

    // ---- epilogue ----
    if (MODE == 4) {
        __syncthreads();                        // protect smem reuse
        float* st = (float*)smem;               // [128 ch][129] fp32
#pragma unroll
        for (int i = 0; i < 2; i++) {
#pragma unroll
            for (int f = 0; f < 4; f++) {
                const float* d = dc[i * 4 + f];
                int rl = wm * 32 + i * 16 + (lid >> 2);
                int cl = wn * 32 + f * 8 + ((lid & 3) << 1);
                float2 bb = *(const float2*)(bias + n0 + cl);
                st[(cl + 0) * 129 + rl]     = d[0] + bb.x;
                st[(cl + 1) * 129 + rl]     = d[1] + bb.y;
                st[(cl + 0) * 129 + rl + 8] = d[2] + bb.x;
                st[(cl + 1) * 129 + rl + 8] = d[3] + bb.y;
            }
        }
        __syncthreads();
        const int b = m0 >> 12, kv0 = m0 & 4095;
        __nv_bfloat16* vth = (__nv_bfloat16*)C0;
        __nv_bfloat16* vtl = (__nv_bfloat16*)C1;
        for (int e = tid; e < 128 * 32; e += 512) {
            int ch = e >> 5, kvg = (e & 31) * 4;
            const float* sr = st + ch * 129 + kvg;
            float v0 = sr[0], v1 = sr[1], v2 = sr[2], v3 = sr[3];
            __nv_bfloat16 h0 = __float2bfloat16(v0), h1 = __float2bfloat16(v1);
            __nv_bfloat16 h2 = __float2bfloat16(v2), h3 = __float2bfloat16(v3);
            long dst = ((long)(b * DQ_ + n0 + ch)) * SKV_ + kv0 + kvg;
            *(uint2*)(vth + dst) = make_uint2(pk2(h0, h1), pk2(h2, h3));
            *(uint2*)(vtl + dst) = make_uint2(
                pk2(__float2bfloat16(v0 - __bfloat162float(h0)),
                    __float2bfloat16(v1 - __bfloat162float(h1))),
                pk2(__float2bfloat16(v2 - __bfloat162float(h2)),
                    __float2bfloat16(v3 - __bfloat162float(h3))));
        }
        return;
    }

    long co = (long)m0 * LDC + n0;
#pragma unroll
    for (int i = 0; i < 2; i++) {
#pragma unroll
        for (int f = 0; f < 4; f++) {
            const float* d = dc[i * 4 + f];
            int rl = wm * 32 + i * 16 + (lid >> 2);
            int cl = wn * 32 + f * 8 + ((lid & 3) << 1);
            float2 bb = *(const float2*)(bias + n0 + cl);
            float v0 = d[0] + bb.x, v1 = d[1] + bb.y;
            float v2 = d[2] + bb.x, v3 = d[3] + bb.y;
            if (MODE == 0) {
                __nv_bfloat16 h0 = __float2bfloat16(v0), h1 = __float2bfloat16(v1);
                __nv_bfloat16 h2 = __float2bfloat16(v2), h3 = __float2bfloat16(v3);
                __nv_bfloat16* ch = (__nv_bfloat16*)C0 + co;
                __nv_bfloat16* cll = (__nv_bfloat16*)C1 + co;
                *(uint32_t*)(ch + (long)rl * LDC + cl)       = pk2(h0, h1);
                *(uint32_t*)(ch + (long)(rl + 8) * LDC + cl) = pk2(h2, h3);
                *(uint32_t*)(cll + (long)rl * LDC + cl) =
                    pk2(__float2bfloat16(v0 - __bfloat162float(h0)),
                        __float2bfloat16(v1 - __bfloat162float(h1)));
                *(uint32_t*)(cll + (long)(rl + 8) * LDC + cl) =
                    pk2(__float2bfloat16(v2 - __bfloat162float(h2)),
                        __float2bfloat16(v3 - __bfloat162float(h3)));
            } else {
                float* cp = (float*)C0 + co;
                *(float2*)(cp + (long)rl * LDC + cl)       = make_float2(v0, v1);
                *(float2*)(cp + (long)(rl + 8) * LDC + cl) = make_float2(v2, v3);
            }
        }
    }
}

// ---------------------------------------------------------------------------
// 256-thread GEMM (attention stages).
// MODE 1: scores per z=(b,h): mask+0.125, write fp32 Wt + tile stats
// MODE 2: PV per z=(b,h): A = fp32 Wt -> inline exp-normalize (writeback), B = vt h/l
// ---------------------------------------------------------------------------
template<int MODE>
__global__ void __launch_bounds__(256, 2)
hgemm_kernel(const __nv_bfloat16* __restrict__ Ah, const __nv_bfloat16* __restrict__ Al,
             const float* __restrict__ Af, int lda,
             const __nv_bfloat16* __restrict__ Bh, const __nv_bfloat16* __restrict__ Bl, int ldb,
             void* __restrict__ C0, void* __restrict__ C1, int Kdim,
             const unsigned char* __restrict__ maskT,
             float* __restrict__ gmax, float* __restrict__ gsum,
             const float* __restrict__ rowM, const float* __restrict__ rowI,
             float* __restrict__ Wtw)
{
    extern __shared__ char smem[];
    constexpr int NT = 64;
    constexpr int NF = NT / 16;
    constexpr unsigned MASKSZ = (MODE == 1) ? 8192u : 0u;
    constexpr unsigned ABY = 128 * 128;
    constexpr unsigned BBY = NT * 128;
    constexpr unsigned BUFSZ = 2 * ABY + 2 * BBY;

    const uint32_t sbase = smem_to_u32(smem);
    const int tid = threadIdx.x;
    const int wid = tid >> 5, lid = tid & 31;
    const int wm = wid & 3, wn = wid >> 2;
    const int m0 = blockIdx.y * 128, n0 = blockIdx.x * NT, z = blockIdx.z;

    const __nv_bfloat16 *Aph = nullptr, *Apl = nullptr, *Bph, *Bpl;
    const float* Afp = nullptr;
    float* Wb = nullptr;
    int LDA, LDB, LDC;
    char *Cp0 = nullptr, *Cp1 = nullptr;
    if (MODE == 1) {
        int b = z >> 4, h = z & 15;
        long ao = ((long)b * SQ_  + m0) * DQ_ + h * DH_;
        long bo = ((long)b * SKV_ + n0) * DQ_ + h * DH_;
        Aph = Ah + ao; Apl = Al + ao; LDA = DQ_;
        Bph = Bh + bo; Bpl = Bl + bo; LDB = DQ_;
        LDC = SKV_;
        Cp0 = (char*)((float*)C0 + ((long)z * SQ_ + m0) * SKV_ + n0);
    } else {
        int b = z >> 4, h = z & 15;
        long wo = ((long)z * SQ_ + m0) * SKV_;
        Afp = Af + wo;  Wb = Wtw + wo;               LDA = SKV_;
        long bo = ((long)(b * DQ_ + h * DH_)) * SKV_;
        Bph = Bh + bo; Bpl = Bl + bo;                LDB = SKV_;
        LDC = DQ_;
        long co = ((long)b * SQ_ + m0) * DQ_ + h * DH_;
        Cp0 = (char*)((__nv_bfloat16*)C0 + co); Cp1 = (char*)((__nv_bfloat16*)C1 + co);
    }

    if (MODE == 1) {
        const unsigned char* msrc = maskT + ((long)(z >> 4) * SQ_ + m0) * SKV_ + n0;
#pragma unroll
        for (int it = 0; it < 8; it++) {
            int idx = it * 1024 + tid * 4;
            int r = idx >> 6, c = idx & 63;
            *(uint32_t*)(smem + idx) = *(const uint32_t*)(msrc + (long)r * SKV_ + c);
        }
    }

    float sM[MODE == 2 ? 8 : 1], sI[MODE == 2 ? 8 : 1];
    if (MODE == 2) {
        long rb = (long)z * SQ_ + m0;
#pragma unroll
        for (int i = 0; i < 8; i++) {
            int r = (tid >> 4) + i * 16;
            sM[i] = rowM[rb + r];
            sI[i] = rowI[rb + r];
        }
    }

    float dc[2 * NF][4];
#pragma unroll
    for (int i = 0; i < 2 * NF; i++)
#pragma unroll
        for (int j = 0; j < 4; j++) dc[i][j] = 0.0f;

    float4 stg[MODE == 2 ? 8 : 1];

    const int ns = Kdim >> 6;

    auto issueB = [&](int s) {
        uint32_t base = sbase + MASKSZ + (unsigned)(s & 1) * BUFSZ;
        cpa_tile<NT>(base + 2 * ABY,       Bph + (long)s * 64, LDB, tid);
        cpa_tile<NT>(base + 2 * ABY + BBY, Bpl + (long)s * 64, LDB, tid);
    };
    auto issueA = [&](int s) {
        uint32_t base = sbase + MASKSZ + (unsigned)(s & 1) * BUFSZ;
        cpa_tile<128>(base,       Aph + (long)s * 64, LDA, tid);
        cpa_tile<128>(base + ABY, Apl + (long)s * 64, LDA, tid);
    };
    auto ldgA = [&](int s) {
        const float* As = Afp + s * 64;
#pragma unroll
        for (int i = 0; i < 8; i++) {
            int f = tid + i * 256, r = f >> 4, cg = (f & 15) << 2;
            stg[i] = *(const float4*)(As + (long)r * LDA + cg);
        }
    };
    auto cvtstsA = [&](int s) {
        char* ah = smem + (size_t)(s & 1) * BUFSZ;
        char* al = ah + ABY;
        float* wb = Wb + s * 64;
#pragma unroll
        for (int i = 0; i < 8; i++) {
            int f = tid + i * 256, r = f >> 4, cg = (f & 15) << 2;
            float4 v = stg[i];
            float4 w;
            w.x = __expf(v.x - sM[i]) * sI[i];
            w.y = __expf(v.y - sM[i]) * sI[i];
            w.z = __expf(v.z - sM[i]) * sI[i];
            w.w = __expf(v.w - sM[i]) * sI[i];
            *(float4*)(wb + (long)r * LDA + cg) = w;
            cvt1(w, ah, al, r, cg);
        }
    };

    auto compute = [&](int buf) {
        const uint32_t sA  = sbase + MASKSZ + (unsigned)buf * BUFSZ;
        const uint32_t sAl = sA + ABY;
        const uint32_t sB  = sA + 2 * ABY;
        const uint32_t sBl = sB + BBY;
        const int lr = lid & 15, hsel = (lid >> 4) << 4;
#pragma unroll
        for (int ks = 0; ks < 4; ks++) {
            const int kb = ks * 32 + hsel;
            uint32_t aH[2][4], aL[2][4];
#pragma unroll
            for (int i = 0; i < 2; i++) {
                unsigned off = SWZ((unsigned)((wm * 32 + i * 16 + lr) * 128 + kb));
                ldm_x4(sA + off, aH[i]);
                ldm_x4(sAl + off, aL[i]);
            }
#pragma unroll
            for (int jj = 0; jj < NF / 2; jj++) {
                unsigned off = SWZ((unsigned)((wn * (NT / 2) + jj * 16 + lr) * 128 + kb));
                uint32_t bH[4], bL[4];
                ldm_x4(sB + off, bH);
                ldm_x4(sBl + off, bL);
#pragma unroll
                for (int i = 0; i < 2; i++) {
#pragma unroll
                    for (int t = 0; t < 2; t++) {
                        float* d = dc[i * NF + jj * 2 + t];
                        mma_bf16(d, aH[i], bH[t], bH[t + 2]);
                        mma_bf16(d, aH[i], bL[t], bL[t + 2]);
                        mma_bf16(d, aL[i], bH[t], bH[t + 2]);
                    }
                }
            }
        }
    };

    if (MODE == 2) {
        ldgA(0);
        issueB(0);
        asm volatile("cp.async.commit_group;" ::: "memory");
        cvtstsA(0);
        for (int s = 0; s < ns; s++) {
            if (s + 1 < ns) {
                ldgA(s + 1);
                issueB(s + 1);
                asm volatile("cp.async.commit_group;" ::: "memory");
                asm volatile("cp.async.wait_group 1;" ::: "memory");
            } else {
                asm volatile("cp.async.wait_group 0;" ::: "memory");
            }
            __syncthreads();
            compute(s & 1);
            if (s + 1 < ns) cvtstsA(s + 1);
            __syncthreads();
        }
    } else {
        issueA(0); issueB(0);
        asm volatile("cp.async.commit_group;" ::: "memory");
        for (int s = 0; s < ns; s++) {
            if (s + 1 < ns) {
                issueA(s + 1); issueB(s + 1);
                asm volatile("cp.async.commit_group;" ::: "memory");
                asm volatile("cp.async.wait_group 1;" ::: "memory");
            } else {
                asm volatile("cp.async.wait_group 0;" ::: "memory");
            }
            __syncthreads();
            compute(s & 1);
            __syncthreads();
        }
    }

    // ---- epilogue ----
    if (MODE == 1) {
        const unsigned char* mk = (const unsigned char*)smem;
        float* pm = (float*)(smem + MASKSZ);
        float* ps = pm + 256;
        float* cm = ps + 256;
        float* cp = (float*)Cp0;
        float rmax[2][2];
#pragma unroll
        for (int i = 0; i < 2; i++) {
            rmax[i][0] = -3.4e38f; rmax[i][1] = -3.4e38f;
            int rl = wm * 32 + i * 16 + (lid >> 2);
#pragma unroll
            for (int f = 0; f < NF; f++) {
                int cl = wn * (NT / 2) + f * 8 + ((lid & 3) << 1);
                float* d = dc[i * NF + f];
                d[0] = mk[rl * 64 + cl]           ? -1.0e9f : d[0] * 0.125f;
                d[1] = mk[rl * 64 + cl + 1]       ? -1.0e9f : d[1] * 0.125f;
                d[2] = mk[(rl + 8) * 64 + cl]     ? -1.0e9f : d[2] * 0.125f;
                d[3] = mk[(rl + 8) * 64 + cl + 1] ? -1.0e9f : d[3] * 0.125f;
                rmax[i][0] = fmaxf(rmax[i][0], fmaxf(d[0], d[1]));
                rmax[i][1] = fmaxf(rmax[i][1], fmaxf(d[2], d[3]));
                *(float2*)(cp + (long)rl * LDC + cl)       = make_float2(d[0], d[1]);
                *(float2*)(cp + (long)(rl + 8) * LDC + cl) = make_float2(d[2], d[3]);
            }
        }
#pragma unroll
        for (int i = 0; i < 2; i++)
#pragma unroll
            for (int s = 0; s < 2; s++) {
                float m = rmax[i][s];
                m = fmaxf(m, __shfl_xor_sync(0xFFFFFFFFu, m, 1));
                m = fmaxf(m, __shfl_xor_sync(0xFFFFFFFFu, m, 2));
                rmax[i][s] = m;
            }
        if ((lid & 3) == 0) {
#pragma unroll
            for (int i = 0; i < 2; i++)
#pragma unroll
                for (int s = 0; s < 2; s++)
                    pm[wn * 128 + wm * 32 + i * 16 + (lid >> 2) + s * 8] = rmax[i][s];
        }
        __syncthreads();
        if (tid < 128) cm[tid] = fmaxf(pm[tid], pm[128 + tid]);
        __syncthreads();
        float rsum[2][2] = {{0.0f, 0.0f}, {0.0f, 0.0f}};
#pragma unroll
        for (int i = 0; i < 2; i++) {
            int rl = wm * 32 + i * 16 + (lid >> 2);
            float mv0 = cm[rl], mv1 = cm[rl + 8];
#pragma unroll
            for (int f = 0; f < NF; f++) {
                float* d = dc[i * NF + f];
                rsum[i][0] += __expf(d[0] - mv0) + __expf(d[1] - mv0);
                rsum[i][1] += __expf(d[2] - mv1) + __expf(d[3] - mv1);
            }
        }
#pragma unroll
        for (int i = 0; i < 2; i++)
#pragma unroll
            for (int s = 0; s < 2; s++) {
                float v = rsum[i][s];
                v += __shfl_xor_sync(0xFFFFFFFFu, v, 1);
                v += __shfl_xor_sync(0xFFFFFFFFu, v, 2);
                rsum[i][s] = v;
            }
        if ((lid & 3) == 0) {
#pragma unroll
            for (int i = 0; i < 2; i++)
#pragma unroll
                for (int s = 0; s < 2; s++)
                    ps[wn * 128 + wm * 32 + i * 16 + (lid >> 2) + s * 8] = rsum[i][s];
        }
        __syncthreads();
        if (tid < 128) {
            long rg = (long)z * SQ_ + m0 + tid;
            gmax[rg * NTILES_ + blockIdx.x] = cm[tid];
            gsum[rg * NTILES_ + blockIdx.x] = ps[tid] + ps[128 + tid];
        }
        return;
    }

#pragma unroll
    for (int i = 0; i < 2; i++) {
#pragma unroll
        for (int f = 0; f < NF; f++) {
            const float* d = dc[i * NF + f];
            int rl = wm * 32 + i * 16 + (lid >> 2);
            int cl = wn * (NT / 2) + f * 8 + ((lid & 3) << 1);
            float v0 = d[0], v1 = d[1], v2 = d[2], v3 = d[3];
            __nv_bfloat16 h0 = __float2bfloat16(v0), h1 = __float2bfloat16(v1);
            __nv_bfloat16 h2 = __float2bfloat16(v2), h3 = __float2bfloat16(v3);
            __nv_bfloat16* ch = (__nv_bfloat16*)Cp0;
            __nv_bfloat16* cll = (__nv_bfloat16*)Cp1;
            *(uint32_t*)(ch + (long)rl * LDC + cl)       = pk2(h0, h1);
            *(uint32_t*)(ch + (long)(rl + 8) * LDC + cl) = pk2(h2, h3);
            *(uint32_t*)(cll + (long)rl * LDC + cl) =
                pk2(__float2bfloat16(v0 - __bfloat162float(h0)),
                    __float2bfloat16(v1 - __bfloat162float(h1)));
            *(uint32_t*)(cll + (long)(rl + 8) * LDC + cl) =
                pk2(__float2bfloat16(v2 - __bfloat162float(h2)),
                    __float2bfloat16(v3 - __bfloat162float(h3)));
        }
    }
}

// ---------------------------------------------------------------------------
// Launch
// ---------------------------------------------------------------------------
extern "C" void kernel_launch(void* const* d_in, const int* in_sizes, int n_in,
                              void* d_out, int out_size)
{
    (void)in_sizes; (void)n_in; (void)out_size;

    const float* Q   = (const float*)d_in[0];
    const float* K   = (const float*)d_in[1];
    const float* V   = (const float*)d_in[2];
    const void*  Msk = d_in[3];
    const float* Wq  = (const float*)d_in[4];
    const float* bq  = (const float*)d_in[5];
    const float* Wk  = (const float*)d_in[6];
    const float* bk  = (const float*)d_in[7];
    const float* Wv  = (const float*)d_in[8];
    const float* bv  = (const float*)d_in[9];
    const float* Wo  = (const float*)d_in[10];
    const float* bo  = (const float*)d_in[11];

    float* out = (float*)d_out;
    float* Wt  = out + (size_t)B_ * SQ_ * DOUT_;

    __nv_bfloat16 *sqh, *sql, *skh, *skl, *svh, *svl;
    __nv_bfloat16 *wqh, *wql, *wkh, *wkl, *wvh, *wvl, *woh, *wol;
    __nv_bfloat16 *qh, *ql, *kh, *kl, *vth, *vtl, *ath, *atl;
    unsigned char* mT;
    float *gmx, *gsm, *rM, *rI;
    cudaGetSymbolAddress((void**)&sqh, g_sqh); cudaGetSymbolAddress((void**)&sql, g_sql);
    cudaGetSymbolAddress((void**)&skh, g_skh); cudaGetSymbolAddress((void**)&skl, g_skl);
    cudaGetSymbolAddress((void**)&svh, g_svh); cudaGetSymbolAddress((void**)&svl, g_svl);
    cudaGetSymbolAddress((void**)&wqh, g_wqh); cudaGetSymbolAddress((void**)&wql, g_wql);
    cudaGetSymbolAddress((void**)&wkh, g_wkh); cudaGetSymbolAddress((void**)&wkl, g_wkl);
    cudaGetSymbolAddress((void**)&wvh, g_wvh); cudaGetSymbolAddress((void**)&wvl, g_wvl);
    cudaGetSymbolAddress((void**)&woh, g_woh); cudaGetSymbolAddress((void**)&wol, g_wol);
    cudaGetSymbolAddress((void**)&qh,  g_qh);  cudaGetSymbolAddress((void**)&ql,  g_ql);
    cudaGetSymbolAddress((void**)&kh,  g_kh);  cudaGetSymbolAddress((void**)&kl,  g_kl);
    cudaGetSymbolAddress((void**)&vth, g_vth); cudaGetSymbolAddress((void**)&vtl, g_vtl);
    cudaGetSymbolAddress((void**)&ath, g_ath); cudaGetSymbolAddress((void**)&atl, g_atl);
    cudaGetSymbolAddress((void**)&mT,  g_maskT);
    cudaGetSymbolAddress((void**)&gmx, g_gmax); cudaGetSymbolAddress((void**)&gsm, g_gsum);
    cudaGetSymbolAddress((void**)&rM,  g_rowM); cudaGetSymbolAddress((void**)&rI,  g_rowI);

    const int SM512 = 3 * 65536;          // 196608: 3-stage 512-thread
    const int SMG   = 2 * 49152;          //  98304: mode 2
    const int SM1   = 8192 + 49152;       //  57344: mode 1
    cudaFuncSetAttribute(hgemm512_kernel<0>, cudaFuncAttributeMaxDynamicSharedMemorySize, SM512);
    cudaFuncSetAttribute(hgemm512_kernel<3>, cudaFuncAttributeMaxDynamicSharedMemorySize, SM512);
    cudaFuncSetAttribute(hgemm512_kernel<4>, cudaFuncAttributeMaxDynamicSharedMemorySize, SM512);
    cudaFuncSetAttribute(hgemm_kernel<1>, cudaFuncAttributeMaxDynamicSharedMemorySize, SM1);
    cudaFuncSetAttribute(hgemm_kernel<2>, cudaFuncAttributeMaxDynamicSharedMemorySize, SMG);

    // 0) probe + merged operand splits + mask transpose
    probe_mask_kernel<<<1, 1>>>((const unsigned int*)Msk);
    split_all_kernel<<<31488, 256>>>(Q, K, V, Wq, Wk, Wv, Wo,
                                     sqh, sql, skh, skl, svh, svl,
                                     wqh, wql, wkh, wkl, wvh, wvl, woh, wol);
    transpose_mask_kernel<<<dim3(SKV_ / 32, SQ_ / 32, B_), dim3(32, 8)>>>(Msk, mT);

    // 1) projections (512-thread 3-stage): Q,K -> bf16 h/l; V -> transposed vt
    hgemm512_kernel<0><<<dim3(DQ_ / 128, (B_ * SQ_) / 128), 512, SM512>>>(
        sqh, sql, DQ_, wqh, wql, DQ_, bq, qh, ql, DQ_, DQ_);
    hgemm512_kernel<0><<<dim3(DQ_ / 128, (B_ * SKV_) / 128), 512, SM512>>>(
        skh, skl, DKV_, wkh, wkl, DKV_, bk, kh, kl, DQ_, DKV_);
    hgemm512_kernel<4><<<dim3(DQ_ / 128, (B_ * SKV_) / 128), 512, SM512>>>(
        svh, svl, DKV_, wvh, wvl, DKV_, bv, vth, vtl, 0, DKV_);

    // 2) masked scores -> fp32 Wt + per-tile softmax stats
    hgemm_kernel<1><<<dim3(SKV_ / 64, SQ_ / 128, B_ * H_), 256, SM1>>>(
        qh, ql, nullptr, 0, kh, kl, 0, Wt, nullptr, DH_,
        mT, gmx, gsm, nullptr, nullptr, nullptr);

    // 3) fold tile stats -> per-row (M, 1/S)
    stats_combine_kernel<<<NROWS_ / 8, 256>>>(gmx, gsm, rM, rI);

    // 4) PV: exp-normalize Wt inline (writeback), GEMM with V^T
    hgemm_kernel<2><<<dim3(1, SQ_ / 128, B_ * H_), 256, SMG>>>(
        nullptr, nullptr, Wt, 0, vth, vtl, 0, ath, atl, SKV_,
        nullptr, nullptr, nullptr, rM, rI, Wt);

    // 5) output projection (512-thread 3-stage) -> fp32 front of d_out
    hgemm512_kernel<3><<<dim3(DOUT_ / 128, (B_ * SQ_) / 128), 512, SM512>>>(
        ath, atl, DQ_, woh, wol, DQ_, bo, out, nullptr, DOUT_, DQ_);
}

// round 15
// speedup vs baseline: 1.1006x; 1.1006x over previous
#include <cuda_runtime.h>
#include <cuda_bf16.h>
#include <cstdint>
#include <math.h>

// Problem constants
#define B_    4
#define SQ_   1024
#define SKV_  4096
#define DQ_   1024
#define DKV_  768
#define H_    16
#define DH_   64
#define DOUT_ 256

#define SWZ(o) ((o) ^ (((o) >> 3) & 0x70))

// ---------------------------------------------------------------------------
// Scratch
// ---------------------------------------------------------------------------
#define AL16 __align__(16)
__device__ AL16 __nv_bfloat16 g_sqh[(size_t)B_ * SQ_  * DQ_ ], g_sql[(size_t)B_ * SQ_  * DQ_ ];
__device__ AL16 __nv_bfloat16 g_skh[(size_t)B_ * SKV_ * DKV_], g_skl[(size_t)B_ * SKV_ * DKV_];
__device__ AL16 __nv_bfloat16 g_svh[(size_t)B_ * SKV_ * DKV_], g_svl[(size_t)B_ * SKV_ * DKV_];
__device__ AL16 __nv_bfloat16 g_wqh[DQ_ * DQ_ ],  g_wql[DQ_ * DQ_ ];
__device__ AL16 __nv_bfloat16 g_wkh[DQ_ * DKV_],  g_wkl[DQ_ * DKV_];
__device__ AL16 __nv_bfloat16 g_wvh[DQ_ * DKV_],  g_wvl[DQ_ * DKV_];
__device__ AL16 __nv_bfloat16 g_woh[DOUT_ * DQ_], g_wol[DOUT_ * DQ_];
__device__ AL16 __nv_bfloat16 g_qh [(size_t)B_ * SQ_  * DQ_], g_ql [(size_t)B_ * SQ_  * DQ_];
__device__ AL16 __nv_bfloat16 g_kh [(size_t)B_ * SKV_ * DQ_], g_kl [(size_t)B_ * SKV_ * DQ_];
__device__ AL16 __nv_bfloat16 g_vth[(size_t)B_ * DQ_ * SKV_], g_vtl[(size_t)B_ * DQ_ * SKV_];
__device__ AL16 __nv_bfloat16 g_ath[(size_t)B_ * SQ_ * DQ_], g_atl[(size_t)B_ * SQ_ * DQ_];
__device__ AL16 unsigned char g_maskT[(size_t)B_ * SQ_ * SKV_];
#define NROWS_ (B_ * H_ * SQ_)
#define NTILES_ 16                         // SKV / 256 (4 kv-tiles per scores CTA)
__device__ AL16 float g_gmax[(size_t)NROWS_ * NTILES_];
__device__ AL16 float g_gsum[(size_t)NROWS_ * NTILES_];
__device__ AL16 float g_rowM[NROWS_];
__device__ AL16 float g_rowI[NROWS_];
__device__ int g_mask_flag;

// ---------------------------------------------------------------------------
// Mask dtype probe
// ---------------------------------------------------------------------------
__global__ void probe_mask_kernel(const unsigned int* __restrict__ m)
{
    if (blockIdx.x != 0 || threadIdx.x != 0) return;
    int is_i32 = 1, is_f32 = 1;
    for (int i = 0; i < 4096; i++) {
        unsigned v = m[i];
        if (v > 1u) is_i32 = 0;
        if (v != 0u && v != 0x3F800000u) is_f32 = 0;
    }
    g_mask_flag = is_i32 ? 1 : (is_f32 ? 2 : 0);
}

__device__ __forceinline__ bool read_mask(const void* m, long i, int flag)
{
    if (flag == 1) return ((const int*)m)[i] != 0;
    if (flag == 2) return ((const float*)m)[i] != 0.0f;
    return ((const unsigned char*)m)[i] != 0;
}

// ---------------------------------------------------------------------------
// Mask transpose: mask[b][kv][q] -> u8 maskT[b][q][kv]
// ---------------------------------------------------------------------------
__global__ __launch_bounds__(256)
void transpose_mask_kernel(const void* __restrict__ mask,
                           unsigned char* __restrict__ maskT)
{
    __shared__ unsigned char t[32][33];
    const int b   = blockIdx.z;
    const int kv0 = blockIdx.x * 32, q0 = blockIdx.y * 32;
    const int x = threadIdx.x, y = threadIdx.y;
    const int flag = g_mask_flag;
#pragma unroll
    for (int i = y; i < 32; i += 8)
        t[i][x] = read_mask(mask, ((long)b * SKV_ + kv0 + i) * SQ_ + q0 + x, flag) ? 1 : 0;
    __syncthreads();
#pragma unroll
    for (int i = y; i < 32; i += 8)
        maskT[((long)b * SQ_ + q0 + i) * SKV_ + kv0 + x] = t[x][i];
}

// ---------------------------------------------------------------------------
// Primitives
// ---------------------------------------------------------------------------
__device__ __forceinline__ uint32_t smem_to_u32(const void* p) {
    uint32_t a;
    asm("{ .reg .u64 t; cvta.to.shared.u64 t, %1; cvt.u32.u64 %0, t; }"
        : "=r"(a) : "l"(p));
    return a;
}

__device__ __forceinline__ void ldm_x4(uint32_t addr, uint32_t* r) {
    asm volatile("ldmatrix.sync.aligned.m8n8.x4.shared.b16 {%0,%1,%2,%3}, [%4];"
                 : "=r"(r[0]), "=r"(r[1]), "=r"(r[2]), "=r"(r[3]) : "r"(addr));
}

__device__ __forceinline__ void mma_bf16(float* d, const uint32_t* a,
                                         uint32_t b0, uint32_t b1) {
    asm volatile(
        "mma.sync.aligned.m16n8k16.row.col.f32.bf16.bf16.f32 "
        "{%0,%1,%2,%3}, {%4,%5,%6,%7}, {%8,%9}, {%0,%1,%2,%3};"
        : "+f"(d[0]), "+f"(d[1]), "+f"(d[2]), "+f"(d[3])
        : "r"(a[0]), "r"(a[1]), "r"(a[2]), "r"(a[3]), "r"(b0), "r"(b1));
}

__device__ __forceinline__ uint32_t pk2(__nv_bfloat16 a, __nv_bfloat16 b)
{
    return (uint32_t)__bfloat16_as_ushort(a) | ((uint32_t)__bfloat16_as_ushort(b) << 16);
}

__device__ __forceinline__ void cvt1(float4 v, char* hb, char* lb, int r, int cg)
{
    __nv_bfloat16 h0 = __float2bfloat16(v.x);
    __nv_bfloat16 h1 = __float2bfloat16(v.y);
    __nv_bfloat16 h2 = __float2bfloat16(v.z);
    __nv_bfloat16 h3 = __float2bfloat16(v.w);
    __nv_bfloat16 l0 = __float2bfloat16(v.x - __bfloat162float(h0));
    __nv_bfloat16 l1 = __float2bfloat16(v.y - __bfloat162float(h1));
    __nv_bfloat16 l2 = __float2bfloat16(v.z - __bfloat162float(h2));
    __nv_bfloat16 l3 = __float2bfloat16(v.w - __bfloat162float(h3));
    unsigned off = SWZ((unsigned)(r * 128 + (cg << 1)));
    *(uint2*)(hb + off) = make_uint2(pk2(h0, h1), pk2(h2, h3));
    *(uint2*)(lb + off) = make_uint2(pk2(l0, l1), pk2(l2, l3));
}

template<int ROWS>
__device__ __forceinline__ void cpa_tile(uint32_t dst, const __nv_bfloat16* src,
                                         int ld, int tid)
{
#pragma unroll
    for (int i = 0; i < ROWS / 32; i++) {
        int f = tid + i * 256;
        int r = f >> 3, c = f & 7;
        uint32_t d = dst + SWZ((unsigned)(r * 128 + c * 16));
        const void* s = src + (long)r * ld + c * 8;
        asm volatile("cp.async.cg.shared.global [%0], [%1], 16;" :: "r"(d), "l"(s));
    }
}

// ---------------------------------------------------------------------------
// Merged fp32 -> bf16 hi/lo split for all 7 operands
// ---------------------------------------------------------------------------
__device__ __forceinline__ void split_body(const float* src,
                                           __nv_bfloat16* h, __nv_bfloat16* l,
                                           long blk, int tid)
{
    long i = (blk * 256 + tid) * 4;
    float4 v = *(const float4*)(src + i);
    __nv_bfloat16 h0 = __float2bfloat16(v.x), h1 = __float2bfloat16(v.y);
    __nv_bfloat16 h2 = __float2bfloat16(v.z), h3 = __float2bfloat16(v.w);
    *(uint2*)(h + i) = make_uint2(pk2(h0, h1), pk2(h2, h3));
    *(uint2*)(l + i) = make_uint2(
        pk2(__float2bfloat16(v.x - __bfloat162float(h0)),
            __float2bfloat16(v.y - __bfloat162float(h1))),
        pk2(__float2bfloat16(v.z - __bfloat162float(h2)),
            __float2bfloat16(v.w - __bfloat162float(h3))));
}

__global__ __launch_bounds__(256)
void split_all_kernel(const float* __restrict__ Q, const float* __restrict__ K,
                      const float* __restrict__ V, const float* __restrict__ Wq,
                      const float* __restrict__ Wk, const float* __restrict__ Wv,
                      const float* __restrict__ Wo,
                      __nv_bfloat16* sqh, __nv_bfloat16* sql,
                      __nv_bfloat16* skh, __nv_bfloat16* skl,
                      __nv_bfloat16* svh, __nv_bfloat16* svl,
                      __nv_bfloat16* wqh, __nv_bfloat16* wql,
                      __nv_bfloat16* wkh, __nv_bfloat16* wkl,
                      __nv_bfloat16* wvh, __nv_bfloat16* wvl,
                      __nv_bfloat16* woh, __nv_bfloat16* wol)
{
    const int bx = blockIdx.x, tid = threadIdx.x;
    if      (bx < 4096)  split_body(Q,  sqh, sql, bx,          tid);
    else if (bx < 16384) split_body(K,  skh, skl, bx - 4096,   tid);
    else if (bx < 28672) split_body(V,  svh, svl, bx - 16384,  tid);
    else if (bx < 29696) split_body(Wq, wqh, wql, bx - 28672,  tid);
    else if (bx < 30464) split_body(Wk, wkh, wkl, bx - 29696,  tid);
    else if (bx < 31232) split_body(Wv, wvh, wvl, bx - 30464,  tid);
    else                 split_body(Wo, woh, wol, bx - 31232,  tid);
}

// ---------------------------------------------------------------------------
// Stats combine: fold 16 tile (max, expsum) per row -> (M, 1/S)
// ---------------------------------------------------------------------------
__global__ __launch_bounds__(256)
void stats_combine_kernel(const float* __restrict__ gmax,
                          const float* __restrict__ gsum,
                          float* __restrict__ rowM, float* __restrict__ rowI)
{
    const int row  = blockIdx.x * 8 + (threadIdx.x >> 5);
    const int lane = threadIdx.x & 31;
    float m = -3.4e38f, s = 0.0f;
    if (lane < NTILES_) {
        m = gmax[(long)row * NTILES_ + lane];
        s = gsum[(long)row * NTILES_ + lane];
    }
    float M = m;
#pragma unroll
    for (int o = 16; o; o >>= 1) M = fmaxf(M, __shfl_xor_sync(0xFFFFFFFFu, M, o));
    float sc = s * __expf(m - M);
#pragma unroll
    for (int o = 16; o; o >>= 1) sc += __shfl_xor_sync(0xFFFFFFFFu, sc, o);
    if (lane == 0) { rowM[row] = M; rowI[row] = 1.0f / sc; }
}

// ---------------------------------------------------------------------------
// Split-MMA burst with pass-major ordering (RAW distance 4)
// d index = i*4 + jj*2 + tt
// ---------------------------------------------------------------------------
__device__ __forceinline__ void mma_burst(float (*dc)[4], int jj,
                                          uint32_t aH[2][4], uint32_t aL[2][4],
                                          uint32_t* bH, uint32_t* bL)
{
#pragma unroll
    for (int p = 0; p < 3; p++) {
#pragma unroll
        for (int i = 0; i < 2; i++) {
#pragma unroll
            for (int tt = 0; tt < 2; tt++) {
                float* d = dc[i * 4 + jj * 2 + tt];
                if (p == 0)      mma_bf16(d, aH[i], bH[tt], bH[tt + 2]);
                else if (p == 1) mma_bf16(d, aH[i], bL[tt], bL[tt + 2]);
                else             mma_bf16(d, aL[i], bH[tt], bH[tt + 2]);
            }
        }
    }
}

// ---------------------------------------------------------------------------
// 256-thread GEMM. D[128, 64] per CTA = A[128,K] @ B[64,K]^T
// MODE 0: projections (Q/K): +bias, write bf16 h/l
// MODE 2: PV per z=(b,h): A = fp32 Wt -> inline exp-normalize (writeback), B = vt h/l
// MODE 3: Wo: +bias, write fp32
// MODE 4: V-projection: +bias, write bf16 h/l TRANSPOSED to vt[b][ch][kv]
// ---------------------------------------------------------------------------
template<int MODE>
__global__ void __launch_bounds__(256, 2)
hgemm_kernel(const __nv_bfloat16* __restrict__ Ah, const __nv_bfloat16* __restrict__ Al,
             const float* __restrict__ Af, int lda,
             const __nv_bfloat16* __restrict__ Bh, const __nv_bfloat16* __restrict__ Bl, int ldb,
             const float* __restrict__ bias,
             void* __restrict__ C0, void* __restrict__ C1, int ldc, int Kdim,
             const float* __restrict__ rowM, const float* __restrict__ rowI,
             float* __restrict__ Wtw)
{
    extern __shared__ char smem[];
    constexpr int NT = 64;
    constexpr int NF = NT / 16;                      // 4
    constexpr unsigned ABY = 128 * 128;
    constexpr unsigned BBY = NT * 128;
    constexpr unsigned BUFSZ = 2 * ABY + 2 * BBY;    // 49152

    const uint32_t sbase = smem_to_u32(smem);
    const int tid = threadIdx.x;
    const int wid = tid >> 5, lid = tid & 31;
    const int wm = wid & 3, wn = wid >> 2;
    const int m0 = blockIdx.y * 128, n0 = blockIdx.x * NT, z = blockIdx.z;

    const __nv_bfloat16 *Aph = nullptr, *Apl = nullptr, *Bph, *Bpl;
    const float* Afp = nullptr;
    float* Wb = nullptr;
    int LDA, LDB, LDC = 0;
    char *Cp0 = nullptr, *Cp1 = nullptr;
    if (MODE == 0 || MODE == 3 || MODE == 4) {
        Aph = Ah + (long)m0 * lda;  Apl = Al + (long)m0 * lda;  LDA = lda;
        Bph = Bh + (long)n0 * ldb;  Bpl = Bl + (long)n0 * ldb;  LDB = ldb;
        LDC = ldc;
        long co = (long)m0 * ldc + n0;
        if (MODE == 0) { Cp0 = (char*)((__nv_bfloat16*)C0 + co); Cp1 = (char*)((__nv_bfloat16*)C1 + co); }
        else if (MODE == 3) { Cp0 = (char*)((float*)C0 + co); }
    } else {
        int b = z >> 4, h = z & 15;
        long wo = ((long)z * SQ_ + m0) * SKV_;
        Afp = Af + wo;  Wb = Wtw + wo;               LDA = SKV_;
        long bo = ((long)(b * DQ_ + h * DH_)) * SKV_;
        Bph = Bh + bo; Bpl = Bl + bo;                LDB = SKV_;
        LDC = DQ_;
        long co = ((long)b * SQ_ + m0) * DQ_ + h * DH_;
        Cp0 = (char*)((__nv_bfloat16*)C0 + co); Cp1 = (char*)((__nv_bfloat16*)C1 + co);
    }

    float sM[MODE == 2 ? 8 : 1], sI[MODE == 2 ? 8 : 1];
    if (MODE == 2) {
        long rb = (long)z * SQ_ + m0;
#pragma unroll
        for (int i = 0; i < 8; i++) {
            int r = (tid >> 4) + i * 16;
            sM[i] = rowM[rb + r];
            sI[i] = rowI[rb + r];
        }
    }

    float dc[2 * NF][4];
#pragma unroll
    for (int i = 0; i < 2 * NF; i++)
#pragma unroll
        for (int j = 0; j < 4; j++) dc[i][j] = 0.0f;

    float4 stg[MODE == 2 ? 8 : 1];

    const int ns = Kdim >> 6;

    auto issueB = [&](int s) {
        uint32_t base = sbase + (unsigned)(s & 1) * BUFSZ;
        cpa_tile<NT>(base + 2 * ABY,       Bph + (long)s * 64, LDB, tid);
        cpa_tile<NT>(base + 2 * ABY + BBY, Bpl + (long)s * 64, LDB, tid);
    };
    auto issueA = [&](int s) {
        uint32_t base = sbase + (unsigned)(s & 1) * BUFSZ;
        cpa_tile<128>(base,       Aph + (long)s * 64, LDA, tid);
        cpa_tile<128>(base + ABY, Apl + (long)s * 64, LDA, tid);
    };
    auto ldgA = [&](int s) {
        const float* As = Afp + s * 64;
#pragma unroll
        for (int i = 0; i < 8; i++) {
            int f = tid + i * 256, r = f >> 4, cg = (f & 15) << 2;
            stg[i] = *(const float4*)(As + (long)r * LDA + cg);
        }
    };
    auto cvtstsA = [&](int s) {
        char* ah = smem + (size_t)(s & 1) * BUFSZ;
        char* al = ah + ABY;
        float* wb = Wb + s * 64;
#pragma unroll
        for (int i = 0; i < 8; i++) {
            int f = tid + i * 256, r = f >> 4, cg = (f & 15) << 2;
            float4 v = stg[i];
            float4 w;
            w.x = __expf(v.x - sM[i]) * sI[i];
            w.y = __expf(v.y - sM[i]) * sI[i];
            w.z = __expf(v.z - sM[i]) * sI[i];
            w.w = __expf(v.w - sM[i]) * sI[i];
            *(float4*)(wb + (long)r * LDA + cg) = w;
            cvt1(w, ah, al, r, cg);
        }
    };

    auto compute = [&](int buf) {
        const uint32_t sA  = sbase + (unsigned)buf * BUFSZ;
        const uint32_t sAl = sA + ABY;
        const uint32_t sB  = sA + 2 * ABY;
        const uint32_t sBl = sB + BBY;
        const int lr = lid & 15, hsel = (lid >> 4) << 4;
#pragma unroll
        for (int ks = 0; ks < 4; ks++) {
            const int kb = ks * 32 + hsel;
            uint32_t aH[2][4], aL[2][4];
#pragma unroll
            for (int i = 0; i < 2; i++) {
                unsigned off = SWZ((unsigned)((wm * 32 + i * 16 + lr) * 128 + kb));
                ldm_x4(sA + off, aH[i]);
                ldm_x4(sAl + off, aL[i]);
            }
#pragma unroll
            for (int jj = 0; jj < NF / 2; jj++) {
                unsigned off = SWZ((unsigned)((wn * (NT / 2) + jj * 16 + lr) * 128 + kb));
                uint32_t bH[4], bL[4];
                ldm_x4(sB + off, bH);
                ldm_x4(sBl + off, bL);
                mma_burst(dc, jj, aH, aL, bH, bL);
            }
        }
    };

    if (MODE == 2) {
        ldgA(0);
        issueB(0);
        asm volatile("cp.async.commit_group;" ::: "memory");
        cvtstsA(0);
        for (int s = 0; s < ns; s++) {
            if (s + 1 < ns) {
                ldgA(s + 1);
                issueB(s + 1);
                asm volatile("cp.async.commit_group;" ::: "memory");
                asm volatile("cp.async.wait_group 1;" ::: "memory");
            } else {
                asm volatile("cp.async.wait_group 0;" ::: "memory");
            }
            __syncthreads();
            compute(s & 1);
            if (s + 1 < ns) cvtstsA(s + 1);
            __syncthreads();
        }
    } else {
        issueA(0); issueB(0);
        asm volatile("cp.async.commit_group;" ::: "memory");
        for (int s = 0; s < ns; s++) {
            if (s + 1 < ns) {
                issueA(s + 1); issueB(s + 1);
                asm volatile("cp.async.commit_group;" ::: "memory");
                asm volatile("cp.async.wait_group 1;" ::: "memory");
            } else {
                asm volatile("cp.async.wait_group 0;" ::: "memory");
            }
            __syncthreads();
            compute(s & 1);
            __syncthreads();
        }
    }

    // ---- epilogue ----
    if (MODE == 4) {
        __syncthreads();
        float* st = (float*)smem;                    // [64 ch][129] fp32
#pragma unroll
        for (int i = 0; i < 2; i++) {
#pragma unroll
            for (int f = 0; f < NF; f++) {
                const float* d = dc[i * NF + f];
                int rl = wm * 32 + i * 16 + (lid >> 2);
                int cl = wn * (NT / 2) + f * 8 + ((lid & 3) << 1);
                float2 bb = *(const float2*)(bias + n0 + cl);
                st[(cl + 0) * 129 + rl]     = d[0] + bb.x;
                st[(cl + 1) * 129 + rl]     = d[1] + bb.y;
                st[(cl + 0) * 129 + rl + 8] = d[2] + bb.x;
                st[(cl + 1) * 129 + rl + 8] = d[3] + bb.y;
            }
        }
        __syncthreads();
        const int b = m0 >> 12, kv0 = m0 & 4095;
        __nv_bfloat16* vth = (__nv_bfloat16*)C0;
        __nv_bfloat16* vtl = (__nv_bfloat16*)C1;
        for (int e = tid; e < 64 * 32; e += 256) {
            int ch = e >> 5, kvg = (e & 31) * 4;
            const float* sr = st + ch * 129 + kvg;
            float v0 = sr[0], v1 = sr[1], v2 = sr[2], v3 = sr[3];
            __nv_bfloat16 h0 = __float2bfloat16(v0), h1 = __float2bfloat16(v1);
            __nv_bfloat16 h2 = __float2bfloat16(v2), h3 = __float2bfloat16(v3);
            long dst = ((long)(b * DQ_ + n0 + ch)) * SKV_ + kv0 + kvg;
            *(uint2*)(vth + dst) = make_uint2(pk2(h0, h1), pk2(h2, h3));
            *(uint2*)(vtl + dst) = make_uint2(
                pk2(__float2bfloat16(v0 - __bfloat162float(h0)),
                    __float2bfloat16(v1 - __bfloat162float(h1))),
                pk2(__float2bfloat16(v2 - __bfloat162float(h2)),
                    __float2bfloat16(v3 - __bfloat162float(h3))));
        }
        return;
    }

#pragma unroll
    for (int i = 0; i < 2; i++) {
#pragma unroll
        for (int f = 0; f < NF; f++) {
            const float* d = dc[i * NF + f];
            int rl = wm * 32 + i * 16 + (lid >> 2);
            int cl = wn * (NT / 2) + f * 8 + ((lid & 3) << 1);
            if (MODE == 0 || MODE == 2) {
                float bx = 0.0f, by = 0.0f;
                if (MODE == 0) { float2 bb = *(const float2*)(bias + n0 + cl); bx = bb.x; by = bb.y; }
                float v0 = d[0] + bx, v1 = d[1] + by;
                float v2 = d[2] + bx, v3 = d[3] + by;
                __nv_bfloat16 h0 = __float2bfloat16(v0), h1 = __float2bfloat16(v1);
                __nv_bfloat16 h2 = __float2bfloat16(v2), h3 = __float2bfloat16(v3);
                __nv_bfloat16* ch = (__nv_bfloat16*)Cp0;
                __nv_bfloat16* cll = (__nv_bfloat16*)Cp1;
                *(uint32_t*)(ch + (long)rl * LDC + cl)       = pk2(h0, h1);
                *(uint32_t*)(ch + (long)(rl + 8) * LDC + cl) = pk2(h2, h3);
                *(uint32_t*)(cll + (long)rl * LDC + cl) =
                    pk2(__float2bfloat16(v0 - __bfloat162float(h0)),
                        __float2bfloat16(v1 - __bfloat162float(h1)));
                *(uint32_t*)(cll + (long)(rl + 8) * LDC + cl) =
                    pk2(__float2bfloat16(v2 - __bfloat162float(h2)),
                        __float2bfloat16(v3 - __bfloat162float(h3)));
            } else {
                float2 bb = *(const float2*)(bias + n0 + cl);
                float* cp = (float*)Cp0;
                *(float2*)(cp + (long)rl * LDC + cl) =
                    make_float2(d[0] + bb.x, d[1] + bb.y);
                *(float2*)(cp + (long)(rl + 8) * LDC + cl) =
                    make_float2(d[2] + bb.x, d[3] + bb.y);
            }
        }
    }
}

// ---------------------------------------------------------------------------
// Scores kernel: per CTA handles q-tile 128 x 4 kv-tiles of 64.
// Q tile staged once; K+mask tiles double-buffered. Running (max, expsum)
// per row kept in registers across tiles; one stat write per CTA.
// Smem: Q h/l 32KB @0; 2 stages x (Kh 8K + Kl 8K + mask 8K) @32768;
//       scratch pm/ps/cm @81920 (2560B). Total 84480 -> 2 CTAs/SM.
// ---------------------------------------------------------------------------
#define SC_STG0 32768u
#define SC_SSTR 24576u
#define SC_SCR  81920u
#define SC_SMEM 84480

__global__ void __launch_bounds__(256, 2)
scores_kernel(const __nv_bfloat16* __restrict__ qh, const __nv_bfloat16* __restrict__ ql,
              const __nv_bfloat16* __restrict__ kh, const __nv_bfloat16* __restrict__ kl,
              const unsigned char* __restrict__ maskT,
              float* __restrict__ Wt,
              float* __restrict__ gmax, float* __restrict__ gsum)
{
    extern __shared__ char smem[];
    const uint32_t sbase = smem_to_u32(smem);
    const int tid = threadIdx.x;
    const int wid = tid >> 5, lid = tid & 31;
    const int wm = wid & 3, wn = wid >> 2;
    const int m0 = blockIdx.y * 128, z = blockIdx.z;
    const int nb = blockIdx.x * 256;                 // 4 kv tiles of 64
    const int b = z >> 4, h = z & 15;

    const __nv_bfloat16* qph = qh + ((long)b * SQ_ + m0) * DQ_ + h * DH_;
    const __nv_bfloat16* qpl = ql + ((long)b * SQ_ + m0) * DQ_ + h * DH_;
    const __nv_bfloat16* kph = kh + ((long)b * SKV_ + nb) * DQ_ + h * DH_;
    const __nv_bfloat16* kpl = kl + ((long)b * SKV_ + nb) * DQ_ + h * DH_;
    const unsigned char* mp  = maskT + ((long)b * SQ_ + m0) * SKV_ + nb;
    float* wtp = Wt + ((long)z * SQ_ + m0) * SKV_ + nb;

    auto issueK = [&](int t) {
        uint32_t base = sbase + SC_STG0 + (unsigned)(t & 1) * SC_SSTR;
        cpa_tile<64>(base,        kph + (long)t * 64 * DQ_, DQ_, tid);
        cpa_tile<64>(base + 8192, kpl + (long)t * 64 * DQ_, DQ_, tid);
        const unsigned char* ms = mp + t * 64;
#pragma unroll
        for (int i = 0; i < 2; i++) {
            int f = tid + i * 256;
            int r = f >> 2, c = (f & 3) * 16;
            uint32_t d = base + 16384u + (unsigned)(r * 64 + c);
            asm volatile("cp.async.cg.shared.global [%0], [%1], 16;"
                         :: "r"(d), "l"(ms + (long)r * SKV_ + c));
        }
        asm volatile("cp.async.commit_group;" ::: "memory");
    };

    // stage Q tile + first K/mask in one group
    cpa_tile<128>(sbase,          qph, DQ_, tid);
    cpa_tile<128>(sbase + 16384u, qpl, DQ_, tid);
    issueK(0);

    float rm = -3.4e38f, rs = 0.0f;                  // running stats (tid<128: row tid)
    const int lr = lid & 15, hsel = (lid >> 4) << 4;

    float* pm = (float*)(smem + SC_SCR);             // [256]
    float* ps = pm + 256;                            // [256]
    float* cm = ps + 256;                            // [128]

    for (int t = 0; t < 4; t++) {
        if (t + 1 < 4) {
            issueK(t + 1);
            asm volatile("cp.async.wait_group 1;" ::: "memory");
        } else {
            asm volatile("cp.async.wait_group 0;" ::: "memory");
        }
        __syncthreads();

        // ---- compute S for this kv tile ----
        float dc[8][4];
#pragma unroll
        for (int j = 0; j < 8; j++)
#pragma unroll
            for (int e = 0; e < 4; e++) dc[j][e] = 0.0f;

        const uint32_t kbse = sbase + SC_STG0 + (unsigned)(t & 1) * SC_SSTR;
#pragma unroll
        for (int ks = 0; ks < 4; ks++) {
            const int kb = ks * 32 + hsel;
            uint32_t aH[2][4], aL[2][4];
#pragma unroll
            for (int i = 0; i < 2; i++) {
                unsigned off = SWZ((unsigned)((wm * 32 + i * 16 + lr) * 128 + kb));
                ldm_x4(sbase + off, aH[i]);
                ldm_x4(sbase + 16384u + off, aL[i]);
            }
#pragma unroll
            for (int jj = 0; jj < 2; jj++) {
                unsigned off = SWZ((unsigned)((wn * 32 + jj * 16 + lr) * 128 + kb));
                uint32_t bH[4], bL[4];
                ldm_x4(kbse + off, bH);
                ldm_x4(kbse + 8192u + off, bL);
                mma_burst(dc, jj, aH, aL, bH, bL);
            }
        }

        // ---- per-tile epilogue: mask+scale, write Wt, tile stats ----
        const unsigned char* mk = (const unsigned char*)(smem + SC_STG0 +
                                   (size_t)(t & 1) * SC_SSTR + 16384);
        float* cp = wtp + t * 64;
        float rmax[2][2];
#pragma unroll
        for (int i = 0; i < 2; i++) {
            rmax[i][0] = -3.4e38f; rmax[i][1] = -3.4e38f;
            int rl = wm * 32 + i * 16 + (lid >> 2);
#pragma unroll
            for (int f = 0; f < 4; f++) {
                int cl = wn * 32 + f * 8 + ((lid & 3) << 1);
                float* d = dc[i * 4 + f];
                d[0] = mk[rl * 64 + cl]           ? -1.0e9f : d[0] * 0.125f;
                d[1] = mk[rl * 64 + cl + 1]       ? -1.0e9f : d[1] * 0.125f;
                d[2] = mk[(rl + 8) * 64 + cl]     ? -1.0e9f : d[2] * 0.125f;
                d[3] = mk[(rl + 8) * 64 + cl + 1] ? -1.0e9f : d[3] * 0.125f;
                rmax[i][0] = fmaxf(rmax[i][0], fmaxf(d[0], d[1]));
                rmax[i][1] = fmaxf(rmax[i][1], fmaxf(d[2], d[3]));
                *(float2*)(cp + (long)rl * SKV_ + cl)       = make_float2(d[0], d[1]);
                *(float2*)(cp + (long)(rl + 8) * SKV_ + cl) = make_float2(d[2], d[3]);
            }
        }
#pragma unroll
        for (int i = 0; i < 2; i++)
#pragma unroll
            for (int s = 0; s < 2; s++) {
                float m = rmax[i][s];
                m = fmaxf(m, __shfl_xor_sync(0xFFFFFFFFu, m, 1));
                m = fmaxf(m, __shfl_xor_sync(0xFFFFFFFFu, m, 2));
                rmax[i][s] = m;
            }
        if ((lid & 3) == 0) {
#pragma unroll
            for (int i = 0; i < 2; i++)
#pragma unroll
                for (int s = 0; s < 2; s++)
                    pm[wn * 128 + wm * 32 + i * 16 + (lid >> 2) + s * 8] = rmax[i][s];
        }
        __syncthreads();
        if (tid < 128) cm[tid] = fmaxf(pm[tid], pm[128 + tid]);
        __syncthreads();
        float rsum[2][2] = {{0.0f, 0.0f}, {0.0f, 0.0f}};
#pragma unroll
        for (int i = 0; i < 2; i++) {
            int rl = wm * 32 + i * 16 + (lid >> 2);
            float mv0 = cm[rl], mv1 = cm[rl + 8];
#pragma unroll
            for (int f = 0; f < 4; f++) {
                float* d = dc[i * 4 + f];
                rsum[i][0] += __expf(d[0] - mv0) + __expf(d[1] - mv0);
                rsum[i][1] += __expf(d[2] - mv1) + __expf(d[3] - mv1);
            }
        }
#pragma unroll
        for (int i = 0; i < 2; i++)
#pragma unroll
            for (int s = 0; s < 2; s++) {
                float v = rsum[i][s];
                v += __shfl_xor_sync(0xFFFFFFFFu, v, 1);
                v += __shfl_xor_sync(0xFFFFFFFFu, v, 2);
                rsum[i][s] = v;
            }
        if ((lid & 3) == 0) {
#pragma unroll
            for (int i = 0; i < 2; i++)
#pragma unroll
                for (int s = 0; s < 2; s++)
                    ps[wn * 128 + wm * 32 + i * 16 + (lid >> 2) + s * 8] = rsum[i][s];
        }
        __syncthreads();
        if (tid < 128) {
            float cmv = cm[tid];
            float sv  = ps[tid] + ps[128 + tid];
            float nm  = fmaxf(rm, cmv);
            rs = rs * __expf(rm - nm) + sv * __expf(cmv - nm);
            rm = nm;
        }
        __syncthreads();                             // release scratch + stage
    }

    if (tid < 128) {
        long rg = (long)z * SQ_ + m0 + tid;
        gmax[rg * NTILES_ + blockIdx.x] = rm;
        gsum[rg * NTILES_ + blockIdx.x] = rs;
    }
}

// ---------------------------------------------------------------------------
// Launch
// ---------------------------------------------------------------------------
extern "C" void kernel_launch(void* const* d_in, const int* in_sizes, int n_in,
                              void* d_out, int out_size)
{
    (void)in_sizes; (void)n_in; (void)out_size;

    const float* Q   = (const float*)d_in[0];
    const float* K   = (const float*)d_in[1];
    const float* V   = (const float*)d_in[2];
    const void*  Msk = d_in[3];
    const float* Wq  = (const float*)d_in[4];
    const float* bq  = (const float*)d_in[5];
    const float* Wk  = (const float*)d_in[6];
    const float* bk  = (const float*)d_in[7];
    const float* Wv  = (const float*)d_in[8];
    const float* bv  = (const float*)d_in[9];
    const float* Wo  = (const float*)d_in[10];
    const float* bo  = (const float*)d_in[11];

    float* out = (float*)d_out;
    float* Wt  = out + (size_t)B_ * SQ_ * DOUT_;

    __nv_bfloat16 *sqh, *sql, *skh, *skl, *svh, *svl;
    __nv_bfloat16 *wqh, *wql, *wkh, *wkl, *wvh, *wvl, *woh, *wol;
    __nv_bfloat16 *qh, *ql, *kh, *kl, *vth, *vtl, *ath, *atl;
    unsigned char* mT;
    float *gmx, *gsm, *rM, *rI;
    cudaGetSymbolAddress((void**)&sqh, g_sqh); cudaGetSymbolAddress((void**)&sql, g_sql);
    cudaGetSymbolAddress((void**)&skh, g_skh); cudaGetSymbolAddress((void**)&skl, g_skl);
    cudaGetSymbolAddress((void**)&svh, g_svh); cudaGetSymbolAddress((void**)&svl, g_svl);
    cudaGetSymbolAddress((void**)&wqh, g_wqh); cudaGetSymbolAddress((void**)&wql, g_wql);
    cudaGetSymbolAddress((void**)&wkh, g_wkh); cudaGetSymbolAddress((void**)&wkl, g_wkl);
    cudaGetSymbolAddress((void**)&wvh, g_wvh); cudaGetSymbolAddress((void**)&wvl, g_wvl);
    cudaGetSymbolAddress((void**)&woh, g_woh); cudaGetSymbolAddress((void**)&wol, g_wol);
    cudaGetSymbolAddress((void**)&qh,  g_qh);  cudaGetSymbolAddress((void**)&ql,  g_ql);
    cudaGetSymbolAddress((void**)&kh,  g_kh);  cudaGetSymbolAddress((void**)&kl,  g_kl);
    cudaGetSymbolAddress((void**)&vth, g_vth); cudaGetSymbolAddress((void**)&vtl, g_vtl);
    cudaGetSymbolAddress((void**)&ath, g_ath); cudaGetSymbolAddress((void**)&atl, g_atl);
    cudaGetSymbolAddress((void**)&mT,  g_maskT);
    cudaGetSymbolAddress((void**)&gmx, g_gmax); cudaGetSymbolAddress((void**)&gsm, g_gsum);
    cudaGetSymbolAddress((void**)&rM,  g_rowM); cudaGetSymbolAddress((void**)&rI,  g_rowI);

    const int SMG = 2 * 49152;            // 98304: modes 0,2,3,4 (2 CTAs/SM)
    cudaFuncSetAttribute(hgemm_kernel<0>, cudaFuncAttributeMaxDynamicSharedMemorySize, SMG);
    cudaFuncSetAttribute(hgemm_kernel<2>, cudaFuncAttributeMaxDynamicSharedMemorySize, SMG);
    cudaFuncSetAttribute(hgemm_kernel<3>, cudaFuncAttributeMaxDynamicSharedMemorySize, SMG);
    cudaFuncSetAttribute(hgemm_kernel<4>, cudaFuncAttributeMaxDynamicSharedMemorySize, SMG);
    cudaFuncSetAttribute(scores_kernel,   cudaFuncAttributeMaxDynamicSharedMemorySize, SC_SMEM);

    // 0) probe + merged operand splits + mask transpose
    probe_mask_kernel<<<1, 1>>>((const unsigned int*)Msk);
    split_all_kernel<<<31488, 256>>>(Q, K, V, Wq, Wk, Wv, Wo,
                                     sqh, sql, skh, skl, svh, svl,
                                     wqh, wql, wkh, wkl, wvh, wvl, woh, wol);
    transpose_mask_kernel<<<dim3(SKV_ / 32, SQ_ / 32, B_), dim3(32, 8)>>>(Msk, mT);

    // 1) projections: Q,K -> bf16 h/l; V -> transposed vt bf16 h/l
    hgemm_kernel<0><<<dim3(DQ_ / 64, (B_ * SQ_) / 128, 1), 256, SMG>>>(
        sqh, sql, nullptr, DQ_, wqh, wql, DQ_, bq, qh, ql, DQ_, DQ_,
        nullptr, nullptr, nullptr);
    hgemm_kernel<0><<<dim3(DQ_ / 64, (B_ * SKV_) / 128, 1), 256, SMG>>>(
        skh, skl, nullptr, DKV_, wkh, wkl, DKV_, bk, kh, kl, DQ_, DKV_,
        nullptr, nullptr, nullptr);
    hgemm_kernel<4><<<dim3(DQ_ / 64, (B_ * SKV_) / 128, 1), 256, SMG>>>(
        svh, svl, nullptr, DKV_, wvh, wvl, DKV_, bv, vth, vtl, 0, DKV_,
        nullptr, nullptr, nullptr);

    // 2) masked scores (4 kv-tiles per CTA) -> fp32 Wt + per-CTA softmax stats
    scores_kernel<<<dim3(SKV_ / 256, SQ_ / 128, B_ * H_), 256, SC_SMEM>>>(
        qh, ql, kh, kl, mT, Wt, gmx, gsm);

    // 3) fold tile stats -> per-row (M, 1/S)
    stats_combine_kernel<<<NROWS_ / 8, 256>>>(gmx, gsm, rM, rI);

    // 4) PV: exp-normalize Wt inline (writeback), GEMM with V^T
    hgemm_kernel<2><<<dim3(1, SQ_ / 128, B_ * H_), 256, SMG>>>(
        nullptr, nullptr, Wt, 0, vth, vtl, 0, nullptr, ath, atl, 0, SKV_,
        rM, rI, Wt);

    // 5) output projection -> fp32 front of d_out
    hgemm_kernel<3><<<dim3(DOUT_ / 64, (B_ * SQ_) / 128, 1), 256, SMG>>>(
        ath, atl, nullptr, DQ_, woh, wol, DQ_, bo, out, nullptr, DOUT_, DQ_,
        nullptr, nullptr, nullptr);
}

// round 17
// speedup vs baseline: 1.1381x; 1.0341x over previous
#include <cuda_runtime.h>
#include <cuda_bf16.h>
#include <cstdint>
#include <math.h>

// Problem constants
#define B_    4
#define SQ_   1024
#define SKV_  4096
#define DQ_   1024
#define DKV_  768
#define H_    16
#define DH_   64
#define DOUT_ 256

#define SWZ(o) ((o) ^ (((o) >> 3) & 0x70))

// ---------------------------------------------------------------------------
// Scratch
// ---------------------------------------------------------------------------
#define AL16 __align__(16)
__device__ AL16 __nv_bfloat16 g_sqh[(size_t)B_ * SQ_  * DQ_ ], g_sql[(size_t)B_ * SQ_  * DQ_ ];
__device__ AL16 __nv_bfloat16 g_skh[(size_t)B_ * SKV_ * DKV_], g_skl[(size_t)B_ * SKV_ * DKV_];
__device__ AL16 __nv_bfloat16 g_svh[(size_t)B_ * SKV_ * DKV_], g_svl[(size_t)B_ * SKV_ * DKV_];
__device__ AL16 __nv_bfloat16 g_wqh[DQ_ * DQ_ ],  g_wql[DQ_ * DQ_ ];
__device__ AL16 __nv_bfloat16 g_wkh[DQ_ * DKV_],  g_wkl[DQ_ * DKV_];
__device__ AL16 __nv_bfloat16 g_wvh[DQ_ * DKV_],  g_wvl[DQ_ * DKV_];
__device__ AL16 __nv_bfloat16 g_woh[DOUT_ * DQ_], g_wol[DOUT_ * DQ_];
__device__ AL16 __nv_bfloat16 g_qh [(size_t)B_ * SQ_  * DQ_], g_ql [(size_t)B_ * SQ_  * DQ_];
__device__ AL16 __nv_bfloat16 g_kh [(size_t)B_ * SKV_ * DQ_], g_kl [(size_t)B_ * SKV_ * DQ_];
__device__ AL16 __nv_bfloat16 g_vth[(size_t)B_ * DQ_ * SKV_], g_vtl[(size_t)B_ * DQ_ * SKV_];
__device__ AL16 __nv_bfloat16 g_ath[(size_t)B_ * SQ_ * DQ_], g_atl[(size_t)B_ * SQ_ * DQ_];
__device__ AL16 unsigned char g_maskT[(size_t)B_ * SQ_ * SKV_];
#define NROWS_ (B_ * H_ * SQ_)
#define NTILES_ 8                          // SKV / 512 (8 kv-tiles per scores CTA)
__device__ AL16 float g_gmax[(size_t)NROWS_ * NTILES_];
__device__ AL16 float g_gsum[(size_t)NROWS_ * NTILES_];
__device__ AL16 float g_rowM[NROWS_];
__device__ AL16 float g_rowI[NROWS_];
__device__ int g_mask_flag;

// ---------------------------------------------------------------------------
// Mask dtype probe
// ---------------------------------------------------------------------------
__global__ void probe_mask_kernel(const unsigned int* __restrict__ m)
{
    if (blockIdx.x != 0 || threadIdx.x != 0) return;
    int is_i32 = 1, is_f32 = 1;
    for (int i = 0; i < 4096; i++) {
        unsigned v = m[i];
        if (v > 1u) is_i32 = 0;
        if (v != 0u && v != 0x3F800000u) is_f32 = 0;
    }
    g_mask_flag = is_i32 ? 1 : (is_f32 ? 2 : 0);
}

__device__ __forceinline__ bool read_mask(const void* m, long i, int flag)
{
    if (flag == 1) return ((const int*)m)[i] != 0;
    if (flag == 2) return ((const float*)m)[i] != 0.0f;
    return ((const unsigned char*)m)[i] != 0;
}

// ---------------------------------------------------------------------------
// Mask transpose: mask[b][kv][q] -> u8 maskT[b][q][kv]
// ---------------------------------------------------------------------------
__global__ __launch_bounds__(256)
void transpose_mask_kernel(const void* __restrict__ mask,
                           unsigned char* __restrict__ maskT)
{
    __shared__ unsigned char t[32][33];
    const int b   = blockIdx.z;
    const int kv0 = blockIdx.x * 32, q0 = blockIdx.y * 32;
    const int x = threadIdx.x, y = threadIdx.y;
    const int flag = g_mask_flag;
#pragma unroll
    for (int i = y; i < 32; i += 8)
        t[i][x] = read_mask(mask, ((long)b * SKV_ + kv0 + i) * SQ_ + q0 + x, flag) ? 1 : 0;
    __syncthreads();
#pragma unroll
    for (int i = y; i < 32; i += 8)
        maskT[((long)b * SQ_ + q0 + i) * SKV_ + kv0 + x] = t[x][i];
}

// ---------------------------------------------------------------------------
// Primitives
// ---------------------------------------------------------------------------
__device__ __forceinline__ uint32_t smem_to_u32(const void* p) {
    uint32_t a;
    asm("{ .reg .u64 t; cvta.to.shared.u64 t, %1; cvt.u32.u64 %0, t; }"
        : "=r"(a) : "l"(p));
    return a;
}

__device__ __forceinline__ void ldm_x4(uint32_t addr, uint32_t* r) {
    asm volatile("ldmatrix.sync.aligned.m8n8.x4.shared.b16 {%0,%1,%2,%3}, [%4];"
                 : "=r"(r[0]), "=r"(r[1]), "=r"(r[2]), "=r"(r[3]) : "r"(addr));
}

__device__ __forceinline__ void mma_bf16(float* d, const uint32_t* a,
                                         uint32_t b0, uint32_t b1) {
    asm volatile(
        "mma.sync.aligned.m16n8k16.row.col.f32.bf16.bf16.f32 "
        "{%0,%1,%2,%3}, {%4,%5,%6,%7}, {%8,%9}, {%0,%1,%2,%3};"
        : "+f"(d[0]), "+f"(d[1]), "+f"(d[2]), "+f"(d[3])
        : "r"(a[0]), "r"(a[1]), "r"(a[2]), "r"(a[3]), "r"(b0), "r"(b1));
}

__device__ __forceinline__ uint32_t pk2(__nv_bfloat16 a, __nv_bfloat16 b)
{
    return (uint32_t)__bfloat16_as_ushort(a) | ((uint32_t)__bfloat16_as_ushort(b) << 16);
}

__device__ __forceinline__ void cvt1(float4 v, char* hb, char* lb, int r, int cg)
{
    __nv_bfloat16 h0 = __float2bfloat16(v.x);
    __nv_bfloat16 h1 = __float2bfloat16(v.y);
    __nv_bfloat16 h2 = __float2bfloat16(v.z);
    __nv_bfloat16 h3 = __float2bfloat16(v.w);
    __nv_bfloat16 l0 = __float2bfloat16(v.x - __bfloat162float(h0));
    __nv_bfloat16 l1 = __float2bfloat16(v.y - __bfloat162float(h1));
    __nv_bfloat16 l2 = __float2bfloat16(v.z - __bfloat162float(h2));
    __nv_bfloat16 l3 = __float2bfloat16(v.w - __bfloat162float(h3));
    unsigned off = SWZ((unsigned)(r * 128 + (cg << 1)));
    *(uint2*)(hb + off) = make_uint2(pk2(h0, h1), pk2(h2, h3));
    *(uint2*)(lb + off) = make_uint2(pk2(l0, l1), pk2(l2, l3));
}

template<int ROWS>
__device__ __forceinline__ void cpa_tile(uint32_t dst, const __nv_bfloat16* src,
                                         int ld, int tid)
{
#pragma unroll
    for (int i = 0; i < ROWS / 32; i++) {
        int f = tid + i * 256;
        int r = f >> 3, c = f & 7;
        uint32_t d = dst + SWZ((unsigned)(r * 128 + c * 16));
        const void* s = src + (long)r * ld + c * 8;
        asm volatile("cp.async.cg.shared.global [%0], [%1], 16;" :: "r"(d), "l"(s));
    }
}

// ---------------------------------------------------------------------------
// Merged fp32 -> bf16 hi/lo split for all 7 operands
// ---------------------------------------------------------------------------
__device__ __forceinline__ void split_body(const float* src,
                                           __nv_bfloat16* h, __nv_bfloat16* l,
                                           long blk, int tid)
{
    long i = (blk * 256 + tid) * 4;
    float4 v = *(const float4*)(src + i);
    __nv_bfloat16 h0 = __float2bfloat16(v.x), h1 = __float2bfloat16(v.y);
    __nv_bfloat16 h2 = __float2bfloat16(v.z), h3 = __float2bfloat16(v.w);
    *(uint2*)(h + i) = make_uint2(pk2(h0, h1), pk2(h2, h3));
    *(uint2*)(l + i) = make_uint2(
        pk2(__float2bfloat16(v.x - __bfloat162float(h0)),
            __float2bfloat16(v.y - __bfloat162float(h1))),
        pk2(__float2bfloat16(v.z - __bfloat162float(h2)),
            __float2bfloat16(v.w - __bfloat162float(h3))));
}

__global__ __launch_bounds__(256)
void split_all_kernel(const float* __restrict__ Q, const float* __restrict__ K,
                      const float* __restrict__ V, const float* __restrict__ Wq,
                      const float* __restrict__ Wk, const float* __restrict__ Wv,
                      const float* __restrict__ Wo,
                      __nv_bfloat16* sqh, __nv_bfloat16* sql,
                      __nv_bfloat16* skh, __nv_bfloat16* skl,
                      __nv_bfloat16* svh, __nv_bfloat16* svl,
                      __nv_bfloat16* wqh, __nv_bfloat16* wql,
                      __nv_bfloat16* wkh, __nv_bfloat16* wkl,
                      __nv_bfloat16* wvh, __nv_bfloat16* wvl,
                      __nv_bfloat16* woh, __nv_bfloat16* wol)
{
    const int bx = blockIdx.x, tid = threadIdx.x;
    if      (bx < 4096)  split_body(Q,  sqh, sql, bx,          tid);
    else if (bx < 16384) split_body(K,  skh, skl, bx - 4096,   tid);
    else if (bx < 28672) split_body(V,  svh, svl, bx - 16384,  tid);
    else if (bx < 29696) split_body(Wq, wqh, wql, bx - 28672,  tid);
    else if (bx < 30464) split_body(Wk, wkh, wkl, bx - 29696,  tid);
    else if (bx < 31232) split_body(Wv, wvh, wvl, bx - 30464,  tid);
    else                 split_body(Wo, woh, wol, bx - 31232,  tid);
}

// ---------------------------------------------------------------------------
// Stats combine: fold NTILES_ tile (max, expsum) per row -> (M, 1/S)
// ---------------------------------------------------------------------------
__global__ __launch_bounds__(256)
void stats_combine_kernel(const float* __restrict__ gmax,
                          const float* __restrict__ gsum,
                          float* __restrict__ rowM, float* __restrict__ rowI)
{
    const int row  = blockIdx.x * 8 + (threadIdx.x >> 5);
    const int lane = threadIdx.x & 31;
    float m = -3.4e38f, s = 0.0f;
    if (lane < NTILES_) {
        m = gmax[(long)row * NTILES_ + lane];
        s = gsum[(long)row * NTILES_ + lane];
    }
    float M = m;
#pragma unroll
    for (int o = 16; o; o >>= 1) M = fmaxf(M, __shfl_xor_sync(0xFFFFFFFFu, M, o));
    float sc = s * __expf(m - M);
#pragma unroll
    for (int o = 16; o; o >>= 1) sc += __shfl_xor_sync(0xFFFFFFFFu, sc, o);
    if (lane == 0) { rowM[row] = M; rowI[row] = 1.0f / sc; }
}

// ---------------------------------------------------------------------------
// Split-MMA burst with pass-major ordering (RAW distance 4)
// ---------------------------------------------------------------------------
__device__ __forceinline__ void mma_burst(float (*dc)[4], int jj,
                                          uint32_t aH[2][4], uint32_t aL[2][4],
                                          uint32_t* bH, uint32_t* bL)
{
#pragma unroll
    for (int p = 0; p < 3; p++) {
#pragma unroll
        for (int i = 0; i < 2; i++) {
#pragma unroll
            for (int tt = 0; tt < 2; tt++) {
                float* d = dc[i * 4 + jj * 2 + tt];
                if (p == 0)      mma_bf16(d, aH[i], bH[tt], bH[tt + 2]);
                else if (p == 1) mma_bf16(d, aH[i], bL[tt], bL[tt + 2]);
                else             mma_bf16(d, aL[i], bH[tt], bH[tt + 2]);
            }
        }
    }
}

// ---------------------------------------------------------------------------
// 256-thread GEMM. D[128, 64] per CTA = A[128,K] @ B[64,K]^T
// MODE 0: projections (Q/K): +bias, write bf16 h/l
// MODE 2: PV per z=(b,h): A = fp32 Wt -> inline exp-normalize (writeback), B = vt h/l
// MODE 3: Wo: +bias, write fp32
// MODE 4: V-projection: +bias, write bf16 h/l TRANSPOSED to vt[b][ch][kv]
// ---------------------------------------------------------------------------
template<int MODE>
__global__ void __launch_bounds__(256, 2)
hgemm_kernel(const __nv_bfloat16* __restrict__ Ah, const __nv_bfloat16* __restrict__ Al,
             const float* __restrict__ Af, int lda,
             const __nv_bfloat16* __restrict__ Bh, const __nv_bfloat16* __restrict__ Bl, int ldb,
             const float* __restrict__ bias,
             void* __restrict__ C0, void* __restrict__ C1, int ldc, int Kdim,
             const float* __restrict__ rowM, const float* __restrict__ rowI,
             float* __restrict__ Wtw)
{
    extern __shared__ char smem[];
    constexpr int NT = 64;
    constexpr int NF = NT / 16;
    constexpr unsigned ABY = 128 * 128;
    constexpr unsigned BBY = NT * 128;
    constexpr unsigned BUFSZ = 2 * ABY + 2 * BBY;

    const uint32_t sbase = smem_to_u32(smem);
    const int tid = threadIdx.x;
    const int wid = tid >> 5, lid = tid & 31;
    const int wm = wid & 3, wn = wid >> 2;
    const int m0 = blockIdx.y * 128, n0 = blockIdx.x * NT, z = blockIdx.z;

    const __nv_bfloat16 *Aph = nullptr, *Apl = nullptr, *Bph, *Bpl;
    const float* Afp = nullptr;
    float* Wb = nullptr;
    int LDA, LDB, LDC = 0;
    char *Cp0 = nullptr, *Cp1 = nullptr;
    if (MODE == 0 || MODE == 3 || MODE == 4) {
        Aph = Ah + (long)m0 * lda;  Apl = Al + (long)m0 * lda;  LDA = lda;
        Bph = Bh + (long)n0 * ldb;  Bpl = Bl + (long)n0 * ldb;  LDB = ldb;
        LDC = ldc;
        long co = (long)m0 * ldc + n0;
        if (MODE == 0) { Cp0 = (char*)((__nv_bfloat16*)C0 + co); Cp1 = (char*)((__nv_bfloat16*)C1 + co); }
        else if (MODE == 3) { Cp0 = (char*)((float*)C0 + co); }
    } else {
        int b = z >> 4, h = z & 15;
        long wo = ((long)z * SQ_ + m0) * SKV_;
        Afp = Af + wo;  Wb = Wtw + wo;               LDA = SKV_;
        long bo = ((long)(b * DQ_ + h * DH_)) * SKV_;
        Bph = Bh + bo; Bpl = Bl + bo;                LDB = SKV_;
        LDC = DQ_;
        long co = ((long)b * SQ_ + m0) * DQ_ + h * DH_;
        Cp0 = (char*)((__nv_bfloat16*)C0 + co); Cp1 = (char*)((__nv_bfloat16*)C1 + co);
    }

    float sM[MODE == 2 ? 8 : 1], sI[MODE == 2 ? 8 : 1];
    if (MODE == 2) {
        long rb = (long)z * SQ_ + m0;
#pragma unroll
        for (int i = 0; i < 8; i++) {
            int r = (tid >> 4) + i * 16;
            sM[i] = rowM[rb + r];
            sI[i] = rowI[rb + r];
        }
    }

    float dc[2 * NF][4];
#pragma unroll
    for (int i = 0; i < 2 * NF; i++)
#pragma unroll
        for (int j = 0; j < 4; j++) dc[i][j] = 0.0f;

    float4 stg[MODE == 2 ? 8 : 1];

    const int ns = Kdim >> 6;

    auto issueB = [&](int s) {
        uint32_t base = sbase + (unsigned)(s & 1) * BUFSZ;
        cpa_tile<NT>(base + 2 * ABY,       Bph + (long)s * 64, LDB, tid);
        cpa_tile<NT>(base + 2 * ABY + BBY, Bpl + (long)s * 64, LDB, tid);
    };
    auto issueA = [&](int s) {
        uint32_t base = sbase + (unsigned)(s & 1) * BUFSZ;
        cpa_tile<128>(base,       Aph + (long)s * 64, LDA, tid);
        cpa_tile<128>(base + ABY, Apl + (long)s * 64, LDA, tid);
    };
    auto ldgA = [&](int s) {
        const float* As = Afp + s * 64;
#pragma unroll
        for (int i = 0; i < 8; i++) {
            int f = tid + i * 256, r = f >> 4, cg = (f & 15) << 2;
            stg[i] = *(const float4*)(As + (long)r * LDA + cg);
        }
    };
    auto cvtstsA = [&](int s) {
        char* ah = smem + (size_t)(s & 1) * BUFSZ;
        char* al = ah + ABY;
        float* wb = Wb + s * 64;
#pragma unroll
        for (int i = 0; i < 8; i++) {
            int f = tid + i * 256, r = f >> 4, cg = (f & 15) << 2;
            float4 v = stg[i];
            float4 w;
            w.x = __expf(v.x - sM[i]) * sI[i];
            w.y = __expf(v.y - sM[i]) * sI[i];
            w.z = __expf(v.z - sM[i]) * sI[i];
            w.w = __expf(v.w - sM[i]) * sI[i];
            *(float4*)(wb + (long)r * LDA + cg) = w;
            cvt1(w, ah, al, r, cg);
        }
    };

    auto compute = [&](int buf) {
        const uint32_t sA  = sbase + (unsigned)buf * BUFSZ;
        const uint32_t sAl = sA + ABY;
        const uint32_t sB  = sA + 2 * ABY;
        const uint32_t sBl = sB + BBY;
        const int lr = lid & 15, hsel = (lid >> 4) << 4;
#pragma unroll
        for (int ks = 0; ks < 4; ks++) {
            const int kb = ks * 32 + hsel;
            uint32_t aH[2][4], aL[2][4];
#pragma unroll
            for (int i = 0; i < 2; i++) {
                unsigned off = SWZ((unsigned)((wm * 32 + i * 16 + lr) * 128 + kb));
                ldm_x4(sA + off, aH[i]);
                ldm_x4(sAl + off, aL[i]);
            }
#pragma unroll
            for (int jj = 0; jj < NF / 2; jj++) {
                unsigned off = SWZ((unsigned)((wn * (NT / 2) + jj * 16 + lr) * 128 + kb));
                uint32_t bH[4], bL[4];
                ldm_x4(sB + off, bH);
                ldm_x4(sBl + off, bL);
                mma_burst(dc, jj, aH, aL, bH, bL);
            }
        }
    };

    if (MODE == 2) {
        ldgA(0);
        issueB(0);
        asm volatile("cp.async.commit_group;" ::: "memory");
        cvtstsA(0);
        for (int s = 0; s < ns; s++) {
            if (s + 1 < ns) {
                ldgA(s + 1);
                issueB(s + 1);
                asm volatile("cp.async.commit_group;" ::: "memory");
                asm volatile("cp.async.wait_group 1;" ::: "memory");
            } else {
                asm volatile("cp.async.wait_group 0;" ::: "memory");
            }
            __syncthreads();
            compute(s & 1);
            if (s + 1 < ns) cvtstsA(s + 1);
            __syncthreads();
        }
    } else {
        issueA(0); issueB(0);
        asm volatile("cp.async.commit_group;" ::: "memory");
        for (int s = 0; s < ns; s++) {
            if (s + 1 < ns) {
                issueA(s + 1); issueB(s + 1);
                asm volatile("cp.async.commit_group;" ::: "memory");
                asm volatile("cp.async.wait_group 1;" ::: "memory");
            } else {
                asm volatile("cp.async.wait_group 0;" ::: "memory");
            }
            __syncthreads();
            compute(s & 1);
            __syncthreads();
        }
    }

    // ---- epilogue ----
    if (MODE == 4) {
        __syncthreads();
        float* st = (float*)smem;                    // [64 ch][129] fp32
#pragma unroll
        for (int i = 0; i < 2; i++) {
#pragma unroll
            for (int f = 0; f < NF; f++) {
                const float* d = dc[i * NF + f];
                int rl = wm * 32 + i * 16 + (lid >> 2);
                int cl = wn * (NT / 2) + f * 8 + ((lid & 3) << 1);
                float2 bb = *(const float2*)(bias + n0 + cl);
                st[(cl + 0) * 129 + rl]     = d[0] + bb.x;
                st[(cl + 1) * 129 + rl]     = d[1] + bb.y;
                st[(cl + 0) * 129 + rl + 8] = d[2] + bb.x;
                st[(cl + 1) * 129 + rl + 8] = d[3] + bb.y;
            }
        }
        __syncthreads();
        const int b = m0 >> 12, kv0 = m0 & 4095;
        __nv_bfloat16* vth = (__nv_bfloat16*)C0;
        __nv_bfloat16* vtl = (__nv_bfloat16*)C1;
        for (int e = tid; e < 64 * 32; e += 256) {
            int ch = e >> 5, kvg = (e & 31) * 4;
            const float* sr = st + ch * 129 + kvg;
            float v0 = sr[0], v1 = sr[1], v2 = sr[2], v3 = sr[3];
            __nv_bfloat16 h0 = __float2bfloat16(v0), h1 = __float2bfloat16(v1);
            __nv_bfloat16 h2 = __float2bfloat16(v2), h3 = __float2bfloat16(v3);
            long dst = ((long)(b * DQ_ + n0 + ch)) * SKV_ + kv0 + kvg;
            *(uint2*)(vth + dst) = make_uint2(pk2(h0, h1), pk2(h2, h3));
            *(uint2*)(vtl + dst) = make_uint2(
                pk2(__float2bfloat16(v0 - __bfloat162float(h0)),
                    __float2bfloat16(v1 - __bfloat162float(h1))),
                pk2(__float2bfloat16(v2 - __bfloat162float(h2)),
                    __float2bfloat16(v3 - __bfloat162float(h3))));
        }
        return;
    }

#pragma unroll
    for (int i = 0; i < 2; i++) {
#pragma unroll
        for (int f = 0; f < NF; f++) {
            const float* d = dc[i * NF + f];
            int rl = wm * 32 + i * 16 + (lid >> 2);
            int cl = wn * (NT / 2) + f * 8 + ((lid & 3) << 1);
            if (MODE == 0 || MODE == 2) {
                float bx = 0.0f, by = 0.0f;
                if (MODE == 0) { float2 bb = *(const float2*)(bias + n0 + cl); bx = bb.x; by = bb.y; }
                float v0 = d[0] + bx, v1 = d[1] + by;
                float v2 = d[2] + bx, v3 = d[3] + by;
                __nv_bfloat16 h0 = __float2bfloat16(v0), h1 = __float2bfloat16(v1);
                __nv_bfloat16 h2 = __float2bfloat16(v2), h3 = __float2bfloat16(v3);
                __nv_bfloat16* ch = (__nv_bfloat16*)Cp0;
                __nv_bfloat16* cll = (__nv_bfloat16*)Cp1;
                *(uint32_t*)(ch + (long)rl * LDC + cl)       = pk2(h0, h1);
                *(uint32_t*)(ch + (long)(rl + 8) * LDC + cl) = pk2(h2, h3);
                *(uint32_t*)(cll + (long)rl * LDC + cl) =
                    pk2(__float2bfloat16(v0 - __bfloat162float(h0)),
                        __float2bfloat16(v1 - __bfloat162float(h1)));
                *(uint32_t*)(cll + (long)(rl + 8) * LDC + cl) =
                    pk2(__float2bfloat16(v2 - __bfloat162float(h2)),
                        __float2bfloat16(v3 - __bfloat162float(h3)));
            } else {
                float2 bb = *(const float2*)(bias + n0 + cl);
                float* cp = (float*)Cp0;
                *(float2*)(cp + (long)rl * LDC + cl) =
                    make_float2(d[0] + bb.x, d[1] + bb.y);
                *(float2*)(cp + (long)(rl + 8) * LDC + cl) =
                    make_float2(d[2] + bb.x, d[3] + bb.y);
            }
        }
    }
}

// ---------------------------------------------------------------------------
// Scores kernel: per CTA q-tile 128 x 8 kv-tiles of 64.
// Warp layout 8(m) x 1(n): each warp owns 16 full rows -> row stats are
// quad-shfl only, zero smem scratch, zero epilogue barriers.
// Smem: Q h/l 32KB @0; 2 stages x (Kh 8K + Kl 8K + mask 8K). Total 81920.
// ---------------------------------------------------------------------------
#define SC_T    8
#define SC_STG0 32768u
#define SC_SSTR 24576u
#define SC_SMEM 81920

__global__ void __launch_bounds__(256, 2)
scores_kernel(const __nv_bfloat16* __restrict__ qh, const __nv_bfloat16* __restrict__ ql,
              const __nv_bfloat16* __restrict__ kh, const __nv_bfloat16* __restrict__ kl,
              const unsigned char* __restrict__ maskT,
              float* __restrict__ Wt,
              float* __restrict__ gmax, float* __restrict__ gsum)
{
    extern __shared__ char smem[];
    const uint32_t sbase = smem_to_u32(smem);
    const int tid = threadIdx.x;
    const int wid = tid >> 5, lid = tid & 31;
    const int m0 = blockIdx.y * 128, z = blockIdx.z;
    const int nb = blockIdx.x * (SC_T * 64);
    const int b = z >> 4, h = z & 15;

    const __nv_bfloat16* qph = qh + ((long)b * SQ_ + m0) * DQ_ + h * DH_;
    const __nv_bfloat16* qpl = ql + ((long)b * SQ_ + m0) * DQ_ + h * DH_;
    const __nv_bfloat16* kph = kh + ((long)b * SKV_ + nb) * DQ_ + h * DH_;
    const __nv_bfloat16* kpl = kl + ((long)b * SKV_ + nb) * DQ_ + h * DH_;
    const unsigned char* mp  = maskT + ((long)b * SQ_ + m0) * SKV_ + nb;
    float* wtp = Wt + ((long)z * SQ_ + m0) * SKV_ + nb;

    auto issueK = [&](int t) {
        uint32_t base = sbase + SC_STG0 + (unsigned)(t & 1) * SC_SSTR;
        cpa_tile<64>(base,        kph + (long)t * 64 * DQ_, DQ_, tid);
        cpa_tile<64>(base + 8192, kpl + (long)t * 64 * DQ_, DQ_, tid);
        const unsigned char* ms = mp + t * 64;
#pragma unroll
        for (int i = 0; i < 2; i++) {
            int f = tid + i * 256;
            int r = f >> 2, c = (f & 3) * 16;
            uint32_t d = base + 16384u + (unsigned)(r * 64 + c);
            asm volatile("cp.async.cg.shared.global [%0], [%1], 16;"
                         :: "r"(d), "l"(ms + (long)r * SKV_ + c));
        }
        asm volatile("cp.async.commit_group;" ::: "memory");
    };

    // stage Q tile + first K/mask in one group
    cpa_tile<128>(sbase,          qph, DQ_, tid);
    cpa_tile<128>(sbase + 16384u, qpl, DQ_, tid);
    issueK(0);

    const int lr = lid & 15, hsel = (lid >> 4) << 4;
    const int qr = lid >> 2;                         // 0..7
    const int r0 = wid * 16 + qr;                    // owned row (and r0+8)

    float rm0 = -3.4e38f, rs0 = 0.0f;
    float rm1 = -3.4e38f, rs1 = 0.0f;

    for (int t = 0; t < SC_T; t++) {
        if (t + 1 < SC_T) {
            issueK(t + 1);
            asm volatile("cp.async.wait_group 1;" ::: "memory");
        } else {
            asm volatile("cp.async.wait_group 0;" ::: "memory");
        }
        __syncthreads();

        // ---- compute S: warp-private rows [wid*16, wid*16+16) x 64 cols ----
        float dc[8][4];
#pragma unroll
        for (int j = 0; j < 8; j++)
#pragma unroll
            for (int e = 0; e < 4; e++) dc[j][e] = 0.0f;

        const uint32_t kbse = sbase + SC_STG0 + (unsigned)(t & 1) * SC_SSTR;
#pragma unroll
        for (int ks = 0; ks < 4; ks++) {
            const int kb = ks * 32 + hsel;
            uint32_t aH[4], aL[4];
            {
                unsigned off = SWZ((unsigned)((wid * 16 + lr) * 128 + kb));
                ldm_x4(sbase + off, aH);
                ldm_x4(sbase + 16384u + off, aL);
            }
            uint32_t bH[4][4], bL[4][4];
#pragma unroll
            for (int jj = 0; jj < 4; jj++) {
                unsigned off = SWZ((unsigned)((jj * 16 + lr) * 128 + kb));
                ldm_x4(kbse + off, bH[jj]);
                ldm_x4(kbse + 8192u + off, bL[jj]);
            }
            // pass-major: RAW distance 8
#pragma unroll
            for (int p = 0; p < 3; p++) {
#pragma unroll
                for (int jj = 0; jj < 4; jj++) {
#pragma unroll
                    for (int tt = 0; tt < 2; tt++) {
                        float* d = dc[jj * 2 + tt];
                        if (p == 0)      mma_bf16(d, aH, bH[jj][tt], bH[jj][tt + 2]);
                        else if (p == 1) mma_bf16(d, aH, bL[jj][tt], bL[jj][tt + 2]);
                        else             mma_bf16(d, aL, bH[jj][tt], bH[jj][tt + 2]);
                    }
                }
            }
        }

        // ---- epilogue: mask+scale, write Wt, warp-local running stats ----
        const unsigned char* mk = (const unsigned char*)(smem + SC_STG0 +
                                   (size_t)(t & 1) * SC_SSTR + 16384);
        float* cp = wtp + t * 64;
        float tm0 = -3.4e38f, tm1 = -3.4e38f;
#pragma unroll
        for (int j = 0; j < 8; j++) {
            int cl = j * 8 + ((lid & 3) << 1);
            float* d = dc[j];
            d[0] = mk[r0 * 64 + cl]           ? -1.0e9f : d[0] * 0.125f;
            d[1] = mk[r0 * 64 + cl + 1]       ? -1.0e9f : d[1] * 0.125f;
            d[2] = mk[(r0 + 8) * 64 + cl]     ? -1.0e9f : d[2] * 0.125f;
            d[3] = mk[(r0 + 8) * 64 + cl + 1] ? -1.0e9f : d[3] * 0.125f;
            tm0 = fmaxf(tm0, fmaxf(d[0], d[1]));
            tm1 = fmaxf(tm1, fmaxf(d[2], d[3]));
            *(float2*)(cp + (long)r0 * SKV_ + cl)       = make_float2(d[0], d[1]);
            *(float2*)(cp + (long)(r0 + 8) * SKV_ + cl) = make_float2(d[2], d[3]);
        }
        tm0 = fmaxf(tm0, __shfl_xor_sync(0xFFFFFFFFu, tm0, 1));
        tm0 = fmaxf(tm0, __shfl_xor_sync(0xFFFFFFFFu, tm0, 2));
        tm1 = fmaxf(tm1, __shfl_xor_sync(0xFFFFFFFFu, tm1, 1));
        tm1 = fmaxf(tm1, __shfl_xor_sync(0xFFFFFFFFu, tm1, 2));
        float nm0 = fmaxf(rm0, tm0), nm1 = fmaxf(rm1, tm1);
        float e0 = 0.0f, e1 = 0.0f;
#pragma unroll
        for (int j = 0; j < 8; j++) {
            const float* d = dc[j];
            e0 += __expf(d[0] - nm0) + __expf(d[1] - nm0);
            e1 += __expf(d[2] - nm1) + __expf(d[3] - nm1);
        }
        e0 += __shfl_xor_sync(0xFFFFFFFFu, e0, 1);
        e0 += __shfl_xor_sync(0xFFFFFFFFu, e0, 2);
        e1 += __shfl_xor_sync(0xFFFFFFFFu, e1, 1);
        e1 += __shfl_xor_sync(0xFFFFFFFFu, e1, 2);
        rs0 = rs0 * __expf(rm0 - nm0) + e0;  rm0 = nm0;
        rs1 = rs1 * __expf(rm1 - nm1) + e1;  rm1 = nm1;

        __syncthreads();                             // release stage buffer
    }

    if ((lid & 3) == 0) {
        long rg = (long)z * SQ_ + m0 + r0;
        gmax[rg * NTILES_ + blockIdx.x] = rm0;
        gsum[rg * NTILES_ + blockIdx.x] = rs0;
        gmax[(rg + 8) * NTILES_ + blockIdx.x] = rm1;
        gsum[(rg + 8) * NTILES_ + blockIdx.x] = rs1;
    }
}

// ---------------------------------------------------------------------------
// Launch
// ---------------------------------------------------------------------------
extern "C" void kernel_launch(void* const* d_in, const int* in_sizes, int n_in,
                              void* d_out, int out_size)
{
    (void)in_sizes; (void)n_in; (void)out_size;

    const float* Q   = (const float*)d_in[0];
    const float* K   = (const float*)d_in[1];
    const float* V   = (const float*)d_in[2];
    const void*  Msk = d_in[3];
    const float* Wq  = (const float*)d_in[4];
    const float* bq  = (const float*)d_in[5];
    const float* Wk  = (const float*)d_in[6];
    const float* bk  = (const float*)d_in[7];
    const float* Wv  = (const float*)d_in[8];
    const float* bv  = (const float*)d_in[9];
    const float* Wo  = (const float*)d_in[10];
    const float* bo  = (const float*)d_in[11];

    float* out = (float*)d_out;
    float* Wt  = out + (size_t)B_ * SQ_ * DOUT_;

    __nv_bfloat16 *sqh, *sql, *skh, *skl, *svh, *svl;
    __nv_bfloat16 *wqh, *wql, *wkh, *wkl, *wvh, *wvl, *woh, *wol;
    __nv_bfloat16 *qh, *ql, *kh, *kl, *vth, *vtl, *ath, *atl;
    unsigned char* mT;
    float *gmx, *gsm, *rM, *rI;
    cudaGetSymbolAddress((void**)&sqh, g_sqh); cudaGetSymbolAddress((void**)&sql, g_sql);
    cudaGetSymbolAddress((void**)&skh, g_skh); cudaGetSymbolAddress((void**)&skl, g_skl);
    cudaGetSymbolAddress((void**)&svh, g_svh); cudaGetSymbolAddress((void**)&svl, g_svl);
    cudaGetSymbolAddress((void**)&wqh, g_wqh); cudaGetSymbolAddress((void**)&wql, g_wql);
    cudaGetSymbolAddress((void**)&wkh, g_wkh); cudaGetSymbolAddress((void**)&wkl, g_wkl);
    cudaGetSymbolAddress((void**)&wvh, g_wvh); cudaGetSymbolAddress((void**)&wvl, g_wvl);
    cudaGetSymbolAddress((void**)&woh, g_woh); cudaGetSymbolAddress((void**)&wol, g_wol);
    cudaGetSymbolAddress((void**)&qh,  g_qh);  cudaGetSymbolAddress((void**)&ql,  g_ql);
    cudaGetSymbolAddress((void**)&kh,  g_kh);  cudaGetSymbolAddress((void**)&kl,  g_kl);
    cudaGetSymbolAddress((void**)&vth, g_vth); cudaGetSymbolAddress((void**)&vtl, g_vtl);
    cudaGetSymbolAddress((void**)&ath, g_ath); cudaGetSymbolAddress((void**)&atl, g_atl);
    cudaGetSymbolAddress((void**)&mT,  g_maskT);
    cudaGetSymbolAddress((void**)&gmx, g_gmax); cudaGetSymbolAddress((void**)&gsm, g_gsum);
    cudaGetSymbolAddress((void**)&rM,  g_rowM); cudaGetSymbolAddress((void**)&rI,  g_rowI);

    const int SMG = 2 * 49152;            // 98304: modes 0,2,3,4 (2 CTAs/SM)
    cudaFuncSetAttribute(hgemm_kernel<0>, cudaFuncAttributeMaxDynamicSharedMemorySize, SMG);
    cudaFuncSetAttribute(hgemm_kernel<2>, cudaFuncAttributeMaxDynamicSharedMemorySize, SMG);
    cudaFuncSetAttribute(hgemm_kernel<3>, cudaFuncAttributeMaxDynamicSharedMemorySize, SMG);
    cudaFuncSetAttribute(hgemm_kernel<4>, cudaFuncAttributeMaxDynamicSharedMemorySize, SMG);
    cudaFuncSetAttribute(scores_kernel,   cudaFuncAttributeMaxDynamicSharedMemorySize, SC_SMEM);

    // 0) probe + merged operand splits + mask transpose
    probe_mask_kernel<<<1, 1>>>((const unsigned int*)Msk);
    split_all_kernel<<<31488, 256>>>(Q, K, V, Wq, Wk, Wv, Wo,
                                     sqh, sql, skh, skl, svh, svl,
                                     wqh, wql, wkh, wkl, wvh, wvl, woh, wol);
    transpose_mask_kernel<<<dim3(SKV_ / 32, SQ_ / 32, B_), dim3(32, 8)>>>(Msk, mT);

    // 1) projections: Q,K -> bf16 h/l; V -> transposed vt bf16 h/l
    hgemm_kernel<0><<<dim3(DQ_ / 64, (B_ * SQ_) / 128, 1), 256, SMG>>>(
        sqh, sql, nullptr, DQ_, wqh, wql, DQ_, bq, qh, ql, DQ_, DQ_,
        nullptr, nullptr, nullptr);
    hgemm_kernel<0><<<dim3(DQ_ / 64, (B_ * SKV_) / 128, 1), 256, SMG>>>(
        skh, skl, nullptr, DKV_, wkh, wkl, DKV_, bk, kh, kl, DQ_, DKV_,
        nullptr, nullptr, nullptr);
    hgemm_kernel<4><<<dim3(DQ_ / 64, (B_ * SKV_) / 128, 1), 256, SMG>>>(
        svh, svl, nullptr, DKV_, wvh, wvl, DKV_, bv, vth, vtl, 0, DKV_,
        nullptr, nullptr, nullptr);

    // 2) masked scores (8 kv-tiles per CTA, warp-private rows) -> Wt + stats
    scores_kernel<<<dim3(SKV_ / (SC_T * 64), SQ_ / 128, B_ * H_), 256, SC_SMEM>>>(
        qh, ql, kh, kl, mT, Wt, gmx, gsm);

    // 3) fold tile stats -> per-row (M, 1/S)
    stats_combine_kernel<<<NROWS_ / 8, 256>>>(gmx, gsm, rM, rI);

    // 4) PV: exp-normalize Wt inline (writeback), GEMM with V^T
    hgemm_kernel<2><<<dim3(1, SQ_ / 128, B_ * H_), 256, SMG>>>(
        nullptr, nullptr, Wt, 0, vth, vtl, 0, nullptr, ath, atl, 0, SKV_,
        rM, rI, Wt);

    // 5) output projection -> fp32 front of d_out
    hgemm_kernel<3><<<dim3(DOUT_ / 64, (B_ * SQ_) / 128, 1), 256, SMG>>>(
        ath, atl, nullptr, DQ_, woh, wol, DQ_, bo, out, nullptr, DOUT_, DQ_,
        nullptr, nullptr, nullptr);
}